// round 14
// baseline (speedup 1.0000x reference)
#include <cuda_runtime.h>
#include <cuda_fp16.h>
#include <cfloat>
#include <cstdint>

#define B_   2
#define S_   2048
#define H_   2048
#define NH_  16
#define NG_  4
#define HD_  128
#define M_   (B_ * S_)
#define KVN_ (NG_ * HD_)

__device__ __align__(256) __half g_Qh[M_ * H_];
__device__ __align__(256) __half g_Kh[M_ * KVN_];
__device__ __align__(256) __half g_Vt[B_ * NG_ * HD_ * S_];   // [b][g][d][t]
__device__ __align__(256) __half g_Xh[M_ * H_];
__device__ __align__(256) __half g_Wqh[H_ * H_];
__device__ __align__(256) __half g_Wkh[KVN_ * H_];
__device__ __align__(256) __half g_Wvh[KVN_ * H_];

// ---------------------------------------------------------------------------
__device__ __forceinline__ uint32_t pkh2(float lo, float hi) {
    uint32_t d;
    asm("cvt.rn.f16x2.f32 %0, %1, %2;" : "=r"(d) : "f"(hi), "f"(lo));
    return d;
}
__device__ __forceinline__ uint32_t ex2h2(uint32_t x) {
    uint32_t d;
    asm("ex2.approx.f16x2 %0, %1;" : "=r"(d) : "r"(x));
    return d;
}
__device__ __forceinline__ uint32_t hadd2u(uint32_t a, uint32_t b) {
    uint32_t d;
    asm("add.f16x2 %0, %1, %2;" : "=r"(d) : "r"(a), "r"(b));
    return d;
}
__device__ __forceinline__ void mma16(float* d, const uint32_t* a, const uint32_t* b) {
    asm volatile(
        "mma.sync.aligned.m16n8k16.row.col.f32.f16.f16.f32 "
        "{%0,%1,%2,%3}, {%4,%5,%6,%7}, {%8,%9}, {%0,%1,%2,%3};"
        : "+f"(d[0]), "+f"(d[1]), "+f"(d[2]), "+f"(d[3])
        : "r"(a[0]), "r"(a[1]), "r"(a[2]), "r"(a[3]), "r"(b[0]), "r"(b[1]));
}
__device__ __forceinline__ void ldsm4(uint32_t& r0, uint32_t& r1,
                                      uint32_t& r2, uint32_t& r3, uint32_t addr) {
    asm volatile("ldmatrix.sync.aligned.m8n8.x4.shared.b16 {%0,%1,%2,%3}, [%4];"
                 : "=r"(r0), "=r"(r1), "=r"(r2), "=r"(r3) : "r"(addr));
}
__device__ __forceinline__ void cp16(uint32_t s, const void* g) {
    asm volatile("cp.async.cg.shared.global [%0], [%1], 16;\n" :: "r"(s), "l"(g));
}
__device__ __forceinline__ void cpcommit() { asm volatile("cp.async.commit_group;\n"); }
template <int N>
__device__ __forceinline__ void cpwait() { asm volatile("cp.async.wait_group %0;\n" :: "n"(N)); }
__device__ __forceinline__ uint32_t s2u(const void* p) {
    uint32_t a;
    asm("{.reg .u64 t; cvta.to.shared.u64 t, %1; cvt.u32.u64 %0, t;}" : "=r"(a) : "l"(p));
    return a;
}

// ---------------------------------------------------------------------------
// fused fp32 -> fp16 conversion of X, Wq, Wk, Wv (8 elems/thread)
// ---------------------------------------------------------------------------
#define CVT_XB   4096
#define CVT_WQB  (CVT_XB + 2048)
#define CVT_WKB  (CVT_WQB + 512)
#define CVT_NB   (CVT_WKB + 512)

__global__ __launch_bounds__(256) void cvt_all(
    const float4* __restrict__ X,  const float4* __restrict__ Wq,
    const float4* __restrict__ Wk, const float4* __restrict__ Wv,
    uint4* __restrict__ Xh, uint4* __restrict__ Wqh,
    uint4* __restrict__ Wkh, uint4* __restrict__ Wvh)
{
    int bid = blockIdx.x;
    const float4* src;
    uint4* dst;
    int base;
    if (bid < CVT_XB)       { src = X;  dst = Xh;  base = bid; }
    else if (bid < CVT_WQB) { src = Wq; dst = Wqh; base = bid - CVT_XB; }
    else if (bid < CVT_WKB) { src = Wk; dst = Wkh; base = bid - CVT_WQB; }
    else                    { src = Wv; dst = Wvh; base = bid - CVT_WKB; }
    int i = base * 256 + threadIdx.x;
    float4 a = src[2 * i], b = src[2 * i + 1];
    uint4 o;
    o.x = pkh2(a.x, a.y); o.y = pkh2(a.z, a.w);
    o.z = pkh2(b.x, b.y); o.w = pkh2(b.z, b.w);
    dst[i] = o;
}

// ---------------------------------------------------------------------------
// GEMM core: fp16 smem, LDSM frags, BK=64, 3-stage cp.async. (round-13)
// ---------------------------------------------------------------------------
#define GROWW 36
#define GTILE (128 * GROWW)
#define GSTAGE (2 * GTILE)
#define GSTAGES 3
#define GEMM_SMEM (GSTAGES * GSTAGE * 4)   // 110592 B

struct GemmAcc { float a[4][4][4]; };

__device__ __forceinline__ void gemm_mainloop(
    const __half* __restrict__ X, const __half* __restrict__ W,
    int bm, int bn, int K, uint32_t smB, GemmAcc& A)
{
    const int t = threadIdx.x;
    const int lane = t & 31;
    const int wid = t >> 5;
    const int wm = (wid & 1) * 64;
    const int wn = (wid >> 1) * 32;
    const int lm = lane >> 3, lr = lane & 7;
    const uint32_t aboff = (uint32_t)(((lm & 1) * 8 + lr) * 144 + (lm >> 1) * 16);
    const uint32_t bboff = (uint32_t)(((lm >> 1) * 8 + lr) * 144 + (lm & 1) * 16);

#pragma unroll
    for (int mt = 0; mt < 4; mt++)
#pragma unroll
        for (int nt = 0; nt < 4; nt++)
#pragma unroll
            for (int r = 0; r < 4; r++) A.a[mt][nt][r] = 0.f;

    const int NIT = K / 64;

    auto stage_load = [&](int slice, int buf) {
        const uint32_t sb = smB + (uint32_t)buf * (GSTAGE * 4);
        const int k0 = slice * 64;
#pragma unroll
        for (int i = 0; i < 4; i++) {
            int fi = t + i * 256;
            int row = fi >> 3, c = fi & 7;
            cp16(sb + (uint32_t)(row * GROWW + c * 4) * 4,
                 X + (size_t)(bm + row) * K + k0 + c * 8);
            cp16(sb + (uint32_t)(GTILE + row * GROWW + c * 4) * 4,
                 W + (size_t)(bn + row) * K + k0 + c * 8);
        }
    };

#pragma unroll
    for (int s = 0; s < GSTAGES - 1; s++) {
        stage_load(s, s);
        cpcommit();
    }

    for (int it = 0; it < NIT; it++) {
        cpwait<GSTAGES - 2>();
        __syncthreads();
        int pf = it + GSTAGES - 1;
        if (pf < NIT) stage_load(pf, pf % GSTAGES);
        cpcommit();

        const uint32_t sb = smB + (uint32_t)(it % GSTAGES) * (GSTAGE * 4);
        const uint32_t aB = sb + (uint32_t)wm * 144 + aboff;
        const uint32_t bB = sb + (uint32_t)GTILE * 4 + (uint32_t)wn * 144 + bboff;
#pragma unroll
        for (int ks = 0; ks < 4; ks++) {
            uint32_t a[4][4], b[4][2];
#pragma unroll
            for (int mt = 0; mt < 4; mt++)
                ldsm4(a[mt][0], a[mt][1], a[mt][2], a[mt][3],
                      aB + (uint32_t)(mt * 16 * 144 + ks * 32));
#pragma unroll
            for (int p = 0; p < 2; p++) {
                uint32_t b0, b1, b2, b3;
                ldsm4(b0, b1, b2, b3, bB + (uint32_t)(p * 16 * 144 + ks * 32));
                b[2 * p][0] = b0; b[2 * p][1] = b1;
                b[2 * p + 1][0] = b2; b[2 * p + 1][1] = b3;
            }
#pragma unroll
            for (int mt = 0; mt < 4; mt++)
#pragma unroll
                for (int nt = 0; nt < 4; nt++)
                    mma16(A.a[mt][nt], a[mt], b[nt]);
        }
    }
}

// Fused Q/K/V projections. blockIdx.x: [0,16) Q, [16,20) K, [20,24) V^T.
__global__ __launch_bounds__(256, 2) void gemm_qkv(
    const __half* __restrict__ X,
    const __half* __restrict__ Wq, const __half* __restrict__ Wk,
    const __half* __restrict__ Wv,
    const float* __restrict__ bq, const float* __restrict__ bk,
    const float* __restrict__ bv,
    __half* __restrict__ Qout, __half* __restrict__ Kout,
    __half* __restrict__ Vt)
{
    extern __shared__ uint32_t gsm[];
    const int x = blockIdx.x;
    const int bm = blockIdx.y * 128;
    int mode, bn;
    const __half* W;
    const float* bias;
    if (x < 16)      { mode = 0; bn = x * 128;        W = Wq; bias = bq; }
    else if (x < 20) { mode = 1; bn = (x - 16) * 128; W = Wk; bias = bk; }
    else             { mode = 2; bn = (x - 20) * 128; W = Wv; bias = bv; }

    GemmAcc A;
    gemm_mainloop(X, W, bm, bn, H_, s2u(gsm), A);

    const int lane = threadIdx.x & 31;
    const int wid = threadIdx.x >> 5;
    const int wm = (wid & 1) * 64, wn = (wid >> 1) * 32;
    const int lg = lane >> 2, lt = lane & 3;
#pragma unroll
    for (int mt = 0; mt < 4; mt++) {
        int row = bm + wm + mt * 16 + lg;
#pragma unroll
        for (int nt = 0; nt < 4; nt++) {
            int col = bn + wn + nt * 8 + lt * 2;
            float2 bs = *(const float2*)&bias[col];
            if (mode == 2) {
#pragma unroll
                for (int rr = 0; rr < 2; rr++) {
                    int r = row + rr * 8;
                    int bb = r >> 11, tt = r & 2047;
#pragma unroll
                    for (int cc = 0; cc < 2; cc++) {
                        int c = col + cc;
                        int g = c >> 7, d = c & 127;
                        float v = A.a[mt][nt][rr * 2 + cc] + (cc ? bs.y : bs.x);
                        Vt[(size_t)(((bb * NG_ + g) * HD_ + d)) * S_ + tt] = __float2half_rn(v);
                    }
                }
            } else {
                uint32_t o0 = pkh2(A.a[mt][nt][0] + bs.x, A.a[mt][nt][1] + bs.y);
                uint32_t o1 = pkh2(A.a[mt][nt][2] + bs.x, A.a[mt][nt][3] + bs.y);
                __half* C = (mode == 0) ? Qout : Kout;
                int N = (mode == 0) ? H_ : KVN_;
                *(uint32_t*)&C[(size_t)row * N + col] = o0;
                *(uint32_t*)&C[(size_t)(row + 8) * N + col] = o1;
            }
        }
    }
}

// ---------------------------------------------------------------------------
// Flash attention, key-split warps, Q fragments in REGISTERS (loop-invariant
// smem traffic removed: -17% crossbar bytes), 3-stage KV pipeline, 1 CTA/SM.
// ---------------------------------------------------------------------------
#define ABM 64
#define ABN 64
#define KSTRW 68
#define VSTRW 36
#define QF_OFF 0
#define QF_WORDS (4 * 8 * 32 * 4)              // 4096
#define KV_OFF QF_WORDS
#define MSK_OFF (ABN * KSTRW + HD_ * VSTRW)    // 8960 words into a buffer
#define KVBUF (MSK_OFF + ABN)                  // 9024 words
#define KVSTAGES 3
#define ATT_SMEM ((KV_OFF + KVSTAGES * KVBUF) * 4)   // 124672 B
#define MRG_STR 132
#define MRG_PAIR (16 * MRG_STR + 64)           // 2176 words per pair

__global__ __launch_bounds__(256) void attn_f16(
    const __half* __restrict__ Q, const __half* __restrict__ K,
    const __half* __restrict__ Vt, const int* __restrict__ amask,
    float* __restrict__ out)
{
    extern __shared__ uint32_t smu[];
    uint32_t* Qf = smu + QF_OFF;
    const uint32_t smB = s2u(smu);

    const int b = blockIdx.z;
    const int h = blockIdx.y;
    const int g = h >> 2;
    const int q0 = blockIdx.x * ABM;
    const int t = threadIdx.x;
    const int lane = t & 31;
    const int wid = t >> 5;
    const int qp = wid >> 1;
    const int half = wid & 1;
    const int lg = lane >> 2;
    const int lt = lane & 3;
    const int lm = lane >> 3, lr = lane & 7;
    const uint32_t kboff = (uint32_t)(((lm >> 1) * 8 + lr) * (KSTRW * 4) + (lm & 1) * 16)
                         + (uint32_t)(half * 32 * KSTRW * 4);
    const uint32_t vboff = (uint32_t)(((lm >> 1) * 8 + lr) * (VSTRW * 4) + (lm & 1) * 16)
                         + (uint32_t)(half * 64);

    const __half* Kbase  = K + (size_t)(b * S_) * KVN_ + g * HD_;
    const __half* Vtbase = Vt + ((size_t)(b * NG_ + g) * HD_) * S_;
    const int* mrow = amask + b * S_;
    const float scl2 = 0.08838834764831845f * 1.4426950408889634f;

    auto tile_load = [&](int kt, int buf) {
        const uint32_t kb = smB + (uint32_t)(KV_OFF + buf * KVBUF) * 4;
        const uint32_t vb = kb + (uint32_t)(ABN * KSTRW) * 4;
        const int kr0 = kt * ABN;
#pragma unroll
        for (int i = 0; i < 4; i++) {
            int fi = t + i * 256;
            int krow = fi >> 4, kc = fi & 15;
            cp16(kb + (uint32_t)(krow * KSTRW + kc * 4) * 4,
                 Kbase + (size_t)(kr0 + krow) * KVN_ + kc * 8);
            int vrow = fi >> 3, vc = fi & 7;
            cp16(vb + (uint32_t)(vrow * VSTRW + vc * 4) * 4,
                 Vtbase + (size_t)vrow * S_ + kr0 + vc * 8);
        }
        if (t < ABN) {
            float* Msm = (float*)(smu + KV_OFF + buf * KVBUF + MSK_OFF);
            Msm[t] = mrow[kr0 + t] ? 0.f : -3.4028234663852886e38f;
        }
    };

    tile_load(0, 0);
    cpcommit();
    tile_load(1, 1);
    cpcommit();

    // Q tile: gmem -> Qf smem (A-fragment layout), then once into registers.
    const __half* Qbase = Q + ((size_t)(b * S_ + q0)) * H_ + h * HD_;
#pragma unroll
    for (int i = 0; i < 4; i++) {
        int fi = t + i * 256;
        int row = fi >> 4, c8 = fi & 15;
        uint4 u = *(const uint4*)(Qbase + (size_t)row * H_ + c8 * 8);
        int w = row >> 4, rr = row & 15;
        int lgw = rr & 7, rh = rr >> 3;
        int ks = c8 >> 1, hi = c8 & 1;
        int reg = rh + 2 * hi;
        uint32_t* p = &Qf[(((w * 8 + ks) * 32) + lgw * 4) * 4 + reg];
        p[0] = u.x; p[4] = u.y; p[8] = u.z; p[12] = u.w;
    }
    __syncthreads();
    uint4 qreg[8];
#pragma unroll
    for (int ks = 0; ks < 8; ks++)
        qreg[ks] = *(const uint4*)&Qf[((qp * 8 + ks) * 32 + lane) * 4];

    float m_run[2] = { -FLT_MAX, -FLT_MAX };
    float l_run[2] = { 0.f, 0.f };
    float Oa[16][4];
#pragma unroll
    for (int nt = 0; nt < 16; nt++)
#pragma unroll
        for (int r = 0; r < 4; r++) Oa[nt][r] = 0.f;

    const int NKT = S_ / ABN;
    for (int kt = 0; kt < NKT; kt++) {
        const int buf = kt % KVSTAGES;
        cpwait<KVSTAGES - 2>();
        __syncthreads();
        int pf = kt + KVSTAGES - 1;
        if (pf < NKT) {
            tile_load(pf, pf % KVSTAGES);
            cpcommit();
        }

        const uint32_t kB = smB + (uint32_t)(KV_OFF + buf * KVBUF) * 4 + kboff;
        const uint32_t vB = smB + (uint32_t)(KV_OFF + buf * KVBUF + ABN * KSTRW) * 4 + vboff;
        const float* Msm = (const float*)(smu + KV_OFF + buf * KVBUF + MSK_OFF);

        // ---- S = Q K^T : 16 rows x 32 keys per warp ------------------------
        float sc[4][4];
#pragma unroll
        for (int nt = 0; nt < 4; nt++)
#pragma unroll
            for (int r = 0; r < 4; r++) sc[nt][r] = 0.f;

#pragma unroll
        for (int ks = 0; ks < 8; ks++) {
            uint32_t a[4] = { qreg[ks].x, qreg[ks].y, qreg[ks].z, qreg[ks].w };
#pragma unroll
            for (int p = 0; p < 2; p++) {
                uint32_t b0, b1, b2, b3;
                ldsm4(b0, b1, b2, b3,
                      kB + (uint32_t)(p * 16 * KSTRW * 4 + ks * 32));
                uint32_t bb0[2] = { b0, b1 }, bb1[2] = { b2, b3 };
                mma16(sc[2 * p], a, bb0);
                mma16(sc[2 * p + 1], a, bb1);
            }
        }

        // ---- scale (log2) + mask (from smem) --------------------------------
#pragma unroll
        for (int nt = 0; nt < 4; nt++) {
            float2 mm = *(const float2*)&Msm[half * 32 + nt * 8 + lt * 2];
            sc[nt][0] = sc[nt][0] * scl2 + mm.x;
            sc[nt][1] = sc[nt][1] * scl2 + mm.y;
            sc[nt][2] = sc[nt][2] * scl2 + mm.x;
            sc[nt][3] = sc[nt][3] * scl2 + mm.y;
        }

        // ---- online softmax, lazy rescale ------------------------------------
        float mloc[2] = { -FLT_MAX, -FLT_MAX };
#pragma unroll
        for (int nt = 0; nt < 4; nt++) {
            mloc[0] = fmaxf(mloc[0], fmaxf(sc[nt][0], sc[nt][1]));
            mloc[1] = fmaxf(mloc[1], fmaxf(sc[nt][2], sc[nt][3]));
        }
#pragma unroll
        for (int off = 1; off <= 2; off <<= 1) {
            mloc[0] = fmaxf(mloc[0], __shfl_xor_sync(0xffffffffu, mloc[0], off));
            mloc[1] = fmaxf(mloc[1], __shfl_xor_sync(0xffffffffu, mloc[1], off));
        }
        bool need = (mloc[0] > m_run[0]) || (mloc[1] > m_run[1]);
        if (__any_sync(0xffffffffu, need)) {
            float mnew[2], alpha[2];
#pragma unroll
            for (int r = 0; r < 2; r++) {
                mnew[r] = fmaxf(m_run[r], mloc[r]);
                alpha[r] = exp2f(m_run[r] - mnew[r]);
                m_run[r] = mnew[r];
            }
            l_run[0] *= alpha[0];
            l_run[1] *= alpha[1];
#pragma unroll
            for (int nt = 0; nt < 16; nt++) {
                Oa[nt][0] *= alpha[0];
                Oa[nt][1] *= alpha[0];
                Oa[nt][2] *= alpha[1];
                Oa[nt][3] *= alpha[1];
            }
        }

        uint32_t ph_lo[4], ph_hi[4];
        uint32_t acc_lo = 0u, acc_hi = 0u;
#pragma unroll
        for (int nt = 0; nt < 4; nt++) {
            ph_lo[nt] = ex2h2(pkh2(sc[nt][0] - m_run[0], sc[nt][1] - m_run[0]));
            ph_hi[nt] = ex2h2(pkh2(sc[nt][2] - m_run[1], sc[nt][3] - m_run[1]));
            acc_lo = hadd2u(acc_lo, ph_lo[nt]);
            acc_hi = hadd2u(acc_hi, ph_hi[nt]);
        }
        __half2 h0 = *reinterpret_cast<__half2*>(&acc_lo);
        __half2 h1 = *reinterpret_cast<__half2*>(&acc_hi);
        float rs[2] = { __low2float(h0) + __high2float(h0),
                        __low2float(h1) + __high2float(h1) };
#pragma unroll
        for (int off = 1; off <= 2; off <<= 1) {
            rs[0] += __shfl_xor_sync(0xffffffffu, rs[0], off);
            rs[1] += __shfl_xor_sync(0xffffffffu, rs[1], off);
        }
        l_run[0] += rs[0];
        l_run[1] += rs[1];

        // ---- O += P V over this warp's 32 keys -------------------------------
#pragma unroll
        for (int ks = 0; ks < 2; ks++) {
            uint32_t a[4] = { ph_lo[2 * ks], ph_hi[2 * ks],
                              ph_lo[2 * ks + 1], ph_hi[2 * ks + 1] };
#pragma unroll
            for (int p = 0; p < 8; p++) {
                uint32_t b0, b1, b2, b3;
                ldsm4(b0, b1, b2, b3,
                      vB + (uint32_t)(p * 16 * VSTRW * 4 + ks * 32));
                uint32_t bb0[2] = { b0, b1 }, bb1[2] = { b2, b3 };
                mma16(Oa[2 * p], a, bb0);
                mma16(Oa[2 * p + 1], a, bb1);
            }
        }
    }

    // ---- merge key halves (reuse dead K/V smem) -----------------------------
    __syncthreads();
    float* Mrg = (float*)(smu + KV_OFF);
    float* pbase = Mrg + qp * MRG_PAIR;
    if (half == 1) {
#pragma unroll
        for (int nt = 0; nt < 16; nt++) {
            int col = nt * 8 + lt * 2;
            *(float2*)&pbase[lg * MRG_STR + col]       = { Oa[nt][0], Oa[nt][1] };
            *(float2*)&pbase[(lg + 8) * MRG_STR + col] = { Oa[nt][2], Oa[nt][3] };
        }
        if (lt == 0) {
            *(float2*)&pbase[16 * MRG_STR + lg * 2]       = { m_run[0], l_run[0] };
            *(float2*)&pbase[16 * MRG_STR + (lg + 8) * 2] = { m_run[1], l_run[1] };
        }
    }
    __syncthreads();
    if (half == 0) {
        float2 mlB0 = *(float2*)&pbase[16 * MRG_STR + lg * 2];
        float2 mlB1 = *(float2*)&pbase[16 * MRG_STR + (lg + 8) * 2];
        float m0 = fmaxf(m_run[0], mlB0.x);
        float m1 = fmaxf(m_run[1], mlB1.x);
        float fA0 = exp2f(m_run[0] - m0), fB0 = exp2f(mlB0.x - m0);
        float fA1 = exp2f(m_run[1] - m1), fB1 = exp2f(mlB1.x - m1);
        float inv0 = 1.f / (l_run[0] * fA0 + mlB0.y * fB0);
        float inv1 = 1.f / (l_run[1] * fA1 + mlB1.y * fB1);

        int row = q0 + qp * 16 + lg;
        float* ob0 = out + ((size_t)(b * S_ + row)) * H_ + h * HD_;
        float* ob1 = out + ((size_t)(b * S_ + row + 8)) * H_ + h * HD_;
#pragma unroll
        for (int nt = 0; nt < 16; nt++) {
            int col = nt * 8 + lt * 2;
            float2 OB0 = *(float2*)&pbase[lg * MRG_STR + col];
            float2 OB1 = *(float2*)&pbase[(lg + 8) * MRG_STR + col];
            float2 o0 = { (Oa[nt][0] * fA0 + OB0.x * fB0) * inv0,
                          (Oa[nt][1] * fA0 + OB0.y * fB0) * inv0 };
            float2 o1 = { (Oa[nt][2] * fA1 + OB1.x * fB1) * inv1,
                          (Oa[nt][3] * fA1 + OB1.y * fB1) * inv1 };
            *(float2*)&ob0[col] = o0;
            *(float2*)&ob1[col] = o1;
        }
    }
}

// ---------------------------------------------------------------------------
extern "C" void kernel_launch(void* const* d_in, const int* in_sizes, int n_in,
                              void* d_out, int out_size)
{
    const float* X     = (const float*)d_in[0];
    const int*   amask = (const int*)  d_in[1];
    const float* Wq    = (const float*)d_in[2];
    const float* bq    = (const float*)d_in[3];
    const float* Wk    = (const float*)d_in[4];
    const float* bk    = (const float*)d_in[5];
    const float* Wv    = (const float*)d_in[6];
    const float* bv    = (const float*)d_in[7];
    float* out = (float*)d_out;

    __half *Qp, *Kp, *Vp, *Xh, *Wqh, *Wkh, *Wvh;
    cudaGetSymbolAddress((void**)&Qp, g_Qh);
    cudaGetSymbolAddress((void**)&Kp, g_Kh);
    cudaGetSymbolAddress((void**)&Vp, g_Vt);
    cudaGetSymbolAddress((void**)&Xh, g_Xh);
    cudaGetSymbolAddress((void**)&Wqh, g_Wqh);
    cudaGetSymbolAddress((void**)&Wkh, g_Wkh);
    cudaGetSymbolAddress((void**)&Wvh, g_Wvh);

    cvt_all<<<CVT_NB, 256>>>((const float4*)X, (const float4*)Wq,
                             (const float4*)Wk, (const float4*)Wv,
                             (uint4*)Xh, (uint4*)Wqh, (uint4*)Wkh, (uint4*)Wvh);

    cudaFuncSetAttribute(gemm_qkv,
                         cudaFuncAttributeMaxDynamicSharedMemorySize, GEMM_SMEM);
    gemm_qkv<<<dim3(24, M_ / 128), 256, GEMM_SMEM>>>(
        Xh, Wqh, Wkh, Wvh, bq, bk, bv, Qp, Kp, Vp);

    cudaFuncSetAttribute(attn_f16,
                         cudaFuncAttributeMaxDynamicSharedMemorySize, ATT_SMEM);
    attn_f16<<<dim3(S_ / ABM, NH_, B_), 256, ATT_SMEM>>>(Qp, Kp, Vp, amask, out);
}

// round 15
// speedup vs baseline: 1.1168x; 1.1168x over previous
#include <cuda_runtime.h>
#include <cuda_fp16.h>
#include <cfloat>
#include <cstdint>

#define B_   2
#define S_   2048
#define H_   2048
#define NH_  16
#define NG_  4
#define HD_  128
#define M_   (B_ * S_)
#define KVN_ (NG_ * HD_)

__device__ __align__(256) __half g_Qh[M_ * H_];
__device__ __align__(256) __half g_Kh[M_ * KVN_];
__device__ __align__(256) __half g_Vt[B_ * NG_ * HD_ * S_];   // [b][g][d][t]
__device__ __align__(256) __half g_Xh[M_ * H_];
__device__ __align__(256) __half g_Wqh[H_ * H_];
__device__ __align__(256) __half g_Wkh[KVN_ * H_];
__device__ __align__(256) __half g_Wvh[KVN_ * H_];

// ---------------------------------------------------------------------------
__device__ __forceinline__ uint32_t pkh2(float lo, float hi) {
    uint32_t d;
    asm("cvt.rn.f16x2.f32 %0, %1, %2;" : "=r"(d) : "f"(hi), "f"(lo));
    return d;
}
__device__ __forceinline__ uint32_t ex2h2(uint32_t x) {
    uint32_t d;
    asm("ex2.approx.f16x2 %0, %1;" : "=r"(d) : "r"(x));
    return d;
}
__device__ __forceinline__ uint32_t hadd2u(uint32_t a, uint32_t b) {
    uint32_t d;
    asm("add.f16x2 %0, %1, %2;" : "=r"(d) : "r"(a), "r"(b));
    return d;
}
__device__ __forceinline__ void mma16(float* d, const uint32_t* a, const uint32_t* b) {
    asm volatile(
        "mma.sync.aligned.m16n8k16.row.col.f32.f16.f16.f32 "
        "{%0,%1,%2,%3}, {%4,%5,%6,%7}, {%8,%9}, {%0,%1,%2,%3};"
        : "+f"(d[0]), "+f"(d[1]), "+f"(d[2]), "+f"(d[3])
        : "r"(a[0]), "r"(a[1]), "r"(a[2]), "r"(a[3]), "r"(b[0]), "r"(b[1]));
}
__device__ __forceinline__ void ldsm4(uint32_t& r0, uint32_t& r1,
                                      uint32_t& r2, uint32_t& r3, uint32_t addr) {
    asm volatile("ldmatrix.sync.aligned.m8n8.x4.shared.b16 {%0,%1,%2,%3}, [%4];"
                 : "=r"(r0), "=r"(r1), "=r"(r2), "=r"(r3) : "r"(addr));
}
__device__ __forceinline__ void cp16(uint32_t s, const void* g) {
    asm volatile("cp.async.cg.shared.global [%0], [%1], 16;\n" :: "r"(s), "l"(g));
}
__device__ __forceinline__ void cpcommit() { asm volatile("cp.async.commit_group;\n"); }
template <int N>
__device__ __forceinline__ void cpwait() { asm volatile("cp.async.wait_group %0;\n" :: "n"(N)); }
__device__ __forceinline__ uint32_t s2u(const void* p) {
    uint32_t a;
    asm("{.reg .u64 t; cvta.to.shared.u64 t, %1; cvt.u32.u64 %0, t;}" : "=r"(a) : "l"(p));
    return a;
}

// ---------------------------------------------------------------------------
// fused fp32 -> fp16 conversion of X, Wq, Wk, Wv (8 elems/thread)
// ---------------------------------------------------------------------------
#define CVT_XB   4096
#define CVT_WQB  (CVT_XB + 2048)
#define CVT_WKB  (CVT_WQB + 512)
#define CVT_NB   (CVT_WKB + 512)

__global__ __launch_bounds__(256) void cvt_all(
    const float4* __restrict__ X,  const float4* __restrict__ Wq,
    const float4* __restrict__ Wk, const float4* __restrict__ Wv,
    uint4* __restrict__ Xh, uint4* __restrict__ Wqh,
    uint4* __restrict__ Wkh, uint4* __restrict__ Wvh)
{
    int bid = blockIdx.x;
    const float4* src;
    uint4* dst;
    int base;
    if (bid < CVT_XB)       { src = X;  dst = Xh;  base = bid; }
    else if (bid < CVT_WQB) { src = Wq; dst = Wqh; base = bid - CVT_XB; }
    else if (bid < CVT_WKB) { src = Wk; dst = Wkh; base = bid - CVT_WQB; }
    else                    { src = Wv; dst = Wvh; base = bid - CVT_WKB; }
    int i = base * 256 + threadIdx.x;
    float4 a = src[2 * i], b = src[2 * i + 1];
    uint4 o;
    o.x = pkh2(a.x, a.y); o.y = pkh2(a.z, a.w);
    o.z = pkh2(b.x, b.y); o.w = pkh2(b.z, b.w);
    dst[i] = o;
}

// ---------------------------------------------------------------------------
// GEMM core: fp16 smem, LDSM frags, BK=64, 3-stage cp.async. (round-13)
// ---------------------------------------------------------------------------
#define GROWW 36
#define GTILE (128 * GROWW)
#define GSTAGE (2 * GTILE)
#define GSTAGES 3
#define GEMM_SMEM (GSTAGES * GSTAGE * 4)   // 110592 B

struct GemmAcc { float a[4][4][4]; };

__device__ __forceinline__ void gemm_mainloop(
    const __half* __restrict__ X, const __half* __restrict__ W,
    int bm, int bn, int K, uint32_t smB, GemmAcc& A)
{
    const int t = threadIdx.x;
    const int lane = t & 31;
    const int wid = t >> 5;
    const int wm = (wid & 1) * 64;
    const int wn = (wid >> 1) * 32;
    const int lm = lane >> 3, lr = lane & 7;
    const uint32_t aboff = (uint32_t)(((lm & 1) * 8 + lr) * 144 + (lm >> 1) * 16);
    const uint32_t bboff = (uint32_t)(((lm >> 1) * 8 + lr) * 144 + (lm & 1) * 16);

#pragma unroll
    for (int mt = 0; mt < 4; mt++)
#pragma unroll
        for (int nt = 0; nt < 4; nt++)
#pragma unroll
            for (int r = 0; r < 4; r++) A.a[mt][nt][r] = 0.f;

    const int NIT = K / 64;

    auto stage_load = [&](int slice, int buf) {
        const uint32_t sb = smB + (uint32_t)buf * (GSTAGE * 4);
        const int k0 = slice * 64;
#pragma unroll
        for (int i = 0; i < 4; i++) {
            int fi = t + i * 256;
            int row = fi >> 3, c = fi & 7;
            cp16(sb + (uint32_t)(row * GROWW + c * 4) * 4,
                 X + (size_t)(bm + row) * K + k0 + c * 8);
            cp16(sb + (uint32_t)(GTILE + row * GROWW + c * 4) * 4,
                 W + (size_t)(bn + row) * K + k0 + c * 8);
        }
    };

#pragma unroll
    for (int s = 0; s < GSTAGES - 1; s++) {
        stage_load(s, s);
        cpcommit();
    }

    for (int it = 0; it < NIT; it++) {
        cpwait<GSTAGES - 2>();
        __syncthreads();
        int pf = it + GSTAGES - 1;
        if (pf < NIT) stage_load(pf, pf % GSTAGES);
        cpcommit();

        const uint32_t sb = smB + (uint32_t)(it % GSTAGES) * (GSTAGE * 4);
        const uint32_t aB = sb + (uint32_t)wm * 144 + aboff;
        const uint32_t bB = sb + (uint32_t)GTILE * 4 + (uint32_t)wn * 144 + bboff;
#pragma unroll
        for (int ks = 0; ks < 4; ks++) {
            uint32_t a[4][4], b[4][2];
#pragma unroll
            for (int mt = 0; mt < 4; mt++)
                ldsm4(a[mt][0], a[mt][1], a[mt][2], a[mt][3],
                      aB + (uint32_t)(mt * 16 * 144 + ks * 32));
#pragma unroll
            for (int p = 0; p < 2; p++) {
                uint32_t b0, b1, b2, b3;
                ldsm4(b0, b1, b2, b3, bB + (uint32_t)(p * 16 * 144 + ks * 32));
                b[2 * p][0] = b0; b[2 * p][1] = b1;
                b[2 * p + 1][0] = b2; b[2 * p + 1][1] = b3;
            }
#pragma unroll
            for (int mt = 0; mt < 4; mt++)
#pragma unroll
                for (int nt = 0; nt < 4; nt++)
                    mma16(A.a[mt][nt], a[mt], b[nt]);
        }
    }
}

// Fused Q/K/V projections. blockIdx.x: [0,16) Q, [16,20) K, [20,24) V^T.
__global__ __launch_bounds__(256, 2) void gemm_qkv(
    const __half* __restrict__ X,
    const __half* __restrict__ Wq, const __half* __restrict__ Wk,
    const __half* __restrict__ Wv,
    const float* __restrict__ bq, const float* __restrict__ bk,
    const float* __restrict__ bv,
    __half* __restrict__ Qout, __half* __restrict__ Kout,
    __half* __restrict__ Vt)
{
    extern __shared__ uint32_t gsm[];
    const int x = blockIdx.x;
    const int bm = blockIdx.y * 128;
    int mode, bn;
    const __half* W;
    const float* bias;
    if (x < 16)      { mode = 0; bn = x * 128;        W = Wq; bias = bq; }
    else if (x < 20) { mode = 1; bn = (x - 16) * 128; W = Wk; bias = bk; }
    else             { mode = 2; bn = (x - 20) * 128; W = Wv; bias = bv; }

    GemmAcc A;
    gemm_mainloop(X, W, bm, bn, H_, s2u(gsm), A);

    const int lane = threadIdx.x & 31;
    const int wid = threadIdx.x >> 5;
    const int wm = (wid & 1) * 64, wn = (wid >> 1) * 32;
    const int lg = lane >> 2, lt = lane & 3;
#pragma unroll
    for (int mt = 0; mt < 4; mt++) {
        int row = bm + wm + mt * 16 + lg;
#pragma unroll
        for (int nt = 0; nt < 4; nt++) {
            int col = bn + wn + nt * 8 + lt * 2;
            float2 bs = *(const float2*)&bias[col];
            if (mode == 2) {
#pragma unroll
                for (int rr = 0; rr < 2; rr++) {
                    int r = row + rr * 8;
                    int bb = r >> 11, tt = r & 2047;
#pragma unroll
                    for (int cc = 0; cc < 2; cc++) {
                        int c = col + cc;
                        int g = c >> 7, d = c & 127;
                        float v = A.a[mt][nt][rr * 2 + cc] + (cc ? bs.y : bs.x);
                        Vt[(size_t)(((bb * NG_ + g) * HD_ + d)) * S_ + tt] = __float2half_rn(v);
                    }
                }
            } else {
                uint32_t o0 = pkh2(A.a[mt][nt][0] + bs.x, A.a[mt][nt][1] + bs.y);
                uint32_t o1 = pkh2(A.a[mt][nt][2] + bs.x, A.a[mt][nt][3] + bs.y);
                __half* C = (mode == 0) ? Qout : Kout;
                int N = (mode == 0) ? H_ : KVN_;
                *(uint32_t*)&C[(size_t)row * N + col] = o0;
                *(uint32_t*)&C[(size_t)(row + 8) * N + col] = o1;
            }
        }
    }
}

// ---------------------------------------------------------------------------
// Flash attention, key-split warps (round-13 structure, 2 CTAs/SM) with a
// hedged Q hoist: 4 of 8 Q fragments live in registers, 4 stay in smem.
// ---------------------------------------------------------------------------
#define ABM 64
#define ABN 64
#define KSTRW 68
#define VSTRW 36
#define QF_OFF 0
#define QF_WORDS (4 * 8 * 32 * 4)              // 4096
#define KV_OFF QF_WORDS
#define MSK_OFF (ABN * KSTRW + HD_ * VSTRW)    // 8960 words into a buffer
#define KVBUF (MSK_OFF + ABN)                  // 9024 words
#define ATT_SMEM ((KV_OFF + 2 * KVBUF) * 4)    // 88576 B
#define MRG_STR 132
#define MRG_PAIR (16 * MRG_STR + 64)           // 2176 words per pair

__global__ __launch_bounds__(256, 2) void attn_f16(
    const __half* __restrict__ Q, const __half* __restrict__ K,
    const __half* __restrict__ Vt, const int* __restrict__ amask,
    float* __restrict__ out)
{
    extern __shared__ uint32_t smu[];
    uint32_t* Qf = smu + QF_OFF;
    const uint32_t smB = s2u(smu);

    const int b = blockIdx.z;
    const int h = blockIdx.y;
    const int g = h >> 2;
    const int q0 = blockIdx.x * ABM;
    const int t = threadIdx.x;
    const int lane = t & 31;
    const int wid = t >> 5;
    const int qp = wid >> 1;
    const int half = wid & 1;
    const int lg = lane >> 2;
    const int lt = lane & 3;
    const int lm = lane >> 3, lr = lane & 7;
    const uint32_t kboff = (uint32_t)(((lm >> 1) * 8 + lr) * (KSTRW * 4) + (lm & 1) * 16)
                         + (uint32_t)(half * 32 * KSTRW * 4);
    const uint32_t vboff = (uint32_t)(((lm >> 1) * 8 + lr) * (VSTRW * 4) + (lm & 1) * 16)
                         + (uint32_t)(half * 64);

    const __half* Kbase  = K + (size_t)(b * S_) * KVN_ + g * HD_;
    const __half* Vtbase = Vt + ((size_t)(b * NG_ + g) * HD_) * S_;
    const int* mrow = amask + b * S_;
    const float scl2 = 0.08838834764831845f * 1.4426950408889634f;

    auto tile_load = [&](int kt, int buf) {
        const uint32_t kb = smB + (uint32_t)(KV_OFF + buf * KVBUF) * 4;
        const uint32_t vb = kb + (uint32_t)(ABN * KSTRW) * 4;
        const int kr0 = kt * ABN;
#pragma unroll
        for (int i = 0; i < 4; i++) {
            int fi = t + i * 256;
            int krow = fi >> 4, kc = fi & 15;
            cp16(kb + (uint32_t)(krow * KSTRW + kc * 4) * 4,
                 Kbase + (size_t)(kr0 + krow) * KVN_ + kc * 8);
            int vrow = fi >> 3, vc = fi & 7;
            cp16(vb + (uint32_t)(vrow * VSTRW + vc * 4) * 4,
                 Vtbase + (size_t)vrow * S_ + kr0 + vc * 8);
        }
        if (t < ABN) {
            float* Msm = (float*)(smu + KV_OFF + buf * KVBUF + MSK_OFF);
            Msm[t] = mrow[kr0 + t] ? 0.f : -3.4028234663852886e38f;
        }
    };

    tile_load(0, 0);
    cpcommit();

    const __half* Qbase = Q + ((size_t)(b * S_ + q0)) * H_ + h * HD_;
#pragma unroll
    for (int i = 0; i < 4; i++) {
        int fi = t + i * 256;
        int row = fi >> 4, c8 = fi & 15;
        uint4 u = *(const uint4*)(Qbase + (size_t)row * H_ + c8 * 8);
        int w = row >> 4, rr = row & 15;
        int lgw = rr & 7, rh = rr >> 3;
        int ks = c8 >> 1, hi = c8 & 1;
        int reg = rh + 2 * hi;
        uint32_t* p = &Qf[(((w * 8 + ks) * 32) + lgw * 4) * 4 + reg];
        p[0] = u.x; p[4] = u.y; p[8] = u.z; p[12] = u.w;
    }
    __syncthreads();
    // hedged hoist: first 4 ks fragments in registers, rest stay in smem
    uint4 qreg[4];
#pragma unroll
    for (int ks = 0; ks < 4; ks++)
        qreg[ks] = *(const uint4*)&Qf[((qp * 8 + ks) * 32 + lane) * 4];

    float m_run[2] = { -FLT_MAX, -FLT_MAX };
    float l_run[2] = { 0.f, 0.f };
    float Oa[16][4];
#pragma unroll
    for (int nt = 0; nt < 16; nt++)
#pragma unroll
        for (int r = 0; r < 4; r++) Oa[nt][r] = 0.f;

    const int NKT = S_ / ABN;
    for (int kt = 0; kt < NKT; kt++) {
        const int buf = kt & 1;
        cpwait<0>();
        __syncthreads();
        if (kt + 1 < NKT) tile_load(kt + 1, buf ^ 1);
        cpcommit();

        const uint32_t kB = smB + (uint32_t)(KV_OFF + buf * KVBUF) * 4 + kboff;
        const uint32_t vB = smB + (uint32_t)(KV_OFF + buf * KVBUF + ABN * KSTRW) * 4 + vboff;
        const float* Msm = (const float*)(smu + KV_OFF + buf * KVBUF + MSK_OFF);

        // ---- S = Q K^T : 16 rows x 32 keys per warp ------------------------
        float sc[4][4];
#pragma unroll
        for (int nt = 0; nt < 4; nt++)
#pragma unroll
            for (int r = 0; r < 4; r++) sc[nt][r] = 0.f;

#pragma unroll
        for (int ks = 0; ks < 8; ks++) {
            uint32_t a[4];
            if (ks < 4) {
                a[0] = qreg[ks].x; a[1] = qreg[ks].y;
                a[2] = qreg[ks].z; a[3] = qreg[ks].w;
            } else {
                uint4 av = *(const uint4*)&Qf[((qp * 8 + ks) * 32 + lane) * 4];
                a[0] = av.x; a[1] = av.y; a[2] = av.z; a[3] = av.w;
            }
#pragma unroll
            for (int p = 0; p < 2; p++) {
                uint32_t b0, b1, b2, b3;
                ldsm4(b0, b1, b2, b3,
                      kB + (uint32_t)(p * 16 * KSTRW * 4 + ks * 32));
                uint32_t bb0[2] = { b0, b1 }, bb1[2] = { b2, b3 };
                mma16(sc[2 * p], a, bb0);
                mma16(sc[2 * p + 1], a, bb1);
            }
        }

        // ---- scale (log2) + mask (from smem) --------------------------------
#pragma unroll
        for (int nt = 0; nt < 4; nt++) {
            float2 mm = *(const float2*)&Msm[half * 32 + nt * 8 + lt * 2];
            sc[nt][0] = sc[nt][0] * scl2 + mm.x;
            sc[nt][1] = sc[nt][1] * scl2 + mm.y;
            sc[nt][2] = sc[nt][2] * scl2 + mm.x;
            sc[nt][3] = sc[nt][3] * scl2 + mm.y;
        }

        // ---- online softmax, lazy rescale ------------------------------------
        float mloc[2] = { -FLT_MAX, -FLT_MAX };
#pragma unroll
        for (int nt = 0; nt < 4; nt++) {
            mloc[0] = fmaxf(mloc[0], fmaxf(sc[nt][0], sc[nt][1]));
            mloc[1] = fmaxf(mloc[1], fmaxf(sc[nt][2], sc[nt][3]));
        }
#pragma unroll
        for (int off = 1; off <= 2; off <<= 1) {
            mloc[0] = fmaxf(mloc[0], __shfl_xor_sync(0xffffffffu, mloc[0], off));
            mloc[1] = fmaxf(mloc[1], __shfl_xor_sync(0xffffffffu, mloc[1], off));
        }
        bool need = (mloc[0] > m_run[0]) || (mloc[1] > m_run[1]);
        if (__any_sync(0xffffffffu, need)) {
            float mnew[2], alpha[2];
#pragma unroll
            for (int r = 0; r < 2; r++) {
                mnew[r] = fmaxf(m_run[r], mloc[r]);
                alpha[r] = exp2f(m_run[r] - mnew[r]);
                m_run[r] = mnew[r];
            }
            l_run[0] *= alpha[0];
            l_run[1] *= alpha[1];
#pragma unroll
            for (int nt = 0; nt < 16; nt++) {
                Oa[nt][0] *= alpha[0];
                Oa[nt][1] *= alpha[0];
                Oa[nt][2] *= alpha[1];
                Oa[nt][3] *= alpha[1];
            }
        }

        uint32_t ph_lo[4], ph_hi[4];
        uint32_t acc_lo = 0u, acc_hi = 0u;
#pragma unroll
        for (int nt = 0; nt < 4; nt++) {
            ph_lo[nt] = ex2h2(pkh2(sc[nt][0] - m_run[0], sc[nt][1] - m_run[0]));
            ph_hi[nt] = ex2h2(pkh2(sc[nt][2] - m_run[1], sc[nt][3] - m_run[1]));
            acc_lo = hadd2u(acc_lo, ph_lo[nt]);
            acc_hi = hadd2u(acc_hi, ph_hi[nt]);
        }
        __half2 h0 = *reinterpret_cast<__half2*>(&acc_lo);
        __half2 h1 = *reinterpret_cast<__half2*>(&acc_hi);
        float rs[2] = { __low2float(h0) + __high2float(h0),
                        __low2float(h1) + __high2float(h1) };
#pragma unroll
        for (int off = 1; off <= 2; off <<= 1) {
            rs[0] += __shfl_xor_sync(0xffffffffu, rs[0], off);
            rs[1] += __shfl_xor_sync(0xffffffffu, rs[1], off);
        }
        l_run[0] += rs[0];
        l_run[1] += rs[1];

        // ---- O += P V over this warp's 32 keys -------------------------------
#pragma unroll
        for (int ks = 0; ks < 2; ks++) {
            uint32_t a[4] = { ph_lo[2 * ks], ph_hi[2 * ks],
                              ph_lo[2 * ks + 1], ph_hi[2 * ks + 1] };
#pragma unroll
            for (int p = 0; p < 8; p++) {
                uint32_t b0, b1, b2, b3;
                ldsm4(b0, b1, b2, b3,
                      vB + (uint32_t)(p * 16 * VSTRW * 4 + ks * 32));
                uint32_t bb0[2] = { b0, b1 }, bb1[2] = { b2, b3 };
                mma16(Oa[2 * p], a, bb0);
                mma16(Oa[2 * p + 1], a, bb1);
            }
        }
    }

    // ---- merge key halves (reuse dead K/V smem) -----------------------------
    __syncthreads();
    float* Mrg = (float*)(smu + KV_OFF);
    float* pbase = Mrg + qp * MRG_PAIR;
    if (half == 1) {
#pragma unroll
        for (int nt = 0; nt < 16; nt++) {
            int col = nt * 8 + lt * 2;
            *(float2*)&pbase[lg * MRG_STR + col]       = { Oa[nt][0], Oa[nt][1] };
            *(float2*)&pbase[(lg + 8) * MRG_STR + col] = { Oa[nt][2], Oa[nt][3] };
        }
        if (lt == 0) {
            *(float2*)&pbase[16 * MRG_STR + lg * 2]       = { m_run[0], l_run[0] };
            *(float2*)&pbase[16 * MRG_STR + (lg + 8) * 2] = { m_run[1], l_run[1] };
        }
    }
    __syncthreads();
    if (half == 0) {
        float2 mlB0 = *(float2*)&pbase[16 * MRG_STR + lg * 2];
        float2 mlB1 = *(float2*)&pbase[16 * MRG_STR + (lg + 8) * 2];
        float m0 = fmaxf(m_run[0], mlB0.x);
        float m1 = fmaxf(m_run[1], mlB1.x);
        float fA0 = exp2f(m_run[0] - m0), fB0 = exp2f(mlB0.x - m0);
        float fA1 = exp2f(m_run[1] - m1), fB1 = exp2f(mlB1.x - m1);
        float inv0 = 1.f / (l_run[0] * fA0 + mlB0.y * fB0);
        float inv1 = 1.f / (l_run[1] * fA1 + mlB1.y * fB1);

        int row = q0 + qp * 16 + lg;
        float* ob0 = out + ((size_t)(b * S_ + row)) * H_ + h * HD_;
        float* ob1 = out + ((size_t)(b * S_ + row + 8)) * H_ + h * HD_;
#pragma unroll
        for (int nt = 0; nt < 16; nt++) {
            int col = nt * 8 + lt * 2;
            float2 OB0 = *(float2*)&pbase[lg * MRG_STR + col];
            float2 OB1 = *(float2*)&pbase[(lg + 8) * MRG_STR + col];
            float2 o0 = { (Oa[nt][0] * fA0 + OB0.x * fB0) * inv0,
                          (Oa[nt][1] * fA0 + OB0.y * fB0) * inv0 };
            float2 o1 = { (Oa[nt][2] * fA1 + OB1.x * fB1) * inv1,
                          (Oa[nt][3] * fA1 + OB1.y * fB1) * inv1 };
            *(float2*)&ob0[col] = o0;
            *(float2*)&ob1[col] = o1;
        }
    }
}

// ---------------------------------------------------------------------------
extern "C" void kernel_launch(void* const* d_in, const int* in_sizes, int n_in,
                              void* d_out, int out_size)
{
    const float* X     = (const float*)d_in[0];
    const int*   amask = (const int*)  d_in[1];
    const float* Wq    = (const float*)d_in[2];
    const float* bq    = (const float*)d_in[3];
    const float* Wk    = (const float*)d_in[4];
    const float* bk    = (const float*)d_in[5];
    const float* Wv    = (const float*)d_in[6];
    const float* bv    = (const float*)d_in[7];
    float* out = (float*)d_out;

    __half *Qp, *Kp, *Vp, *Xh, *Wqh, *Wkh, *Wvh;
    cudaGetSymbolAddress((void**)&Qp, g_Qh);
    cudaGetSymbolAddress((void**)&Kp, g_Kh);
    cudaGetSymbolAddress((void**)&Vp, g_Vt);
    cudaGetSymbolAddress((void**)&Xh, g_Xh);
    cudaGetSymbolAddress((void**)&Wqh, g_Wqh);
    cudaGetSymbolAddress((void**)&Wkh, g_Wkh);
    cudaGetSymbolAddress((void**)&Wvh, g_Wvh);

    cvt_all<<<CVT_NB, 256>>>((const float4*)X, (const float4*)Wq,
                             (const float4*)Wk, (const float4*)Wv,
                             (uint4*)Xh, (uint4*)Wqh, (uint4*)Wkh, (uint4*)Wvh);

    cudaFuncSetAttribute(gemm_qkv,
                         cudaFuncAttributeMaxDynamicSharedMemorySize, GEMM_SMEM);
    gemm_qkv<<<dim3(24, M_ / 128), 256, GEMM_SMEM>>>(
        Xh, Wqh, Wkh, Wvh, bq, bk, bv, Qp, Kp, Vp);

    cudaFuncSetAttribute(attn_f16,
                         cudaFuncAttributeMaxDynamicSharedMemorySize, ATT_SMEM);
    attn_f16<<<dim3(S_ / ABM, NH_, B_), 256, ATT_SMEM>>>(Qp, Kp, Vp, amask, out);
}

// round 16
// speedup vs baseline: 1.1336x; 1.0150x over previous
#include <cuda_runtime.h>
#include <cuda_fp16.h>
#include <cfloat>
#include <cstdint>

#define B_   2
#define S_   2048
#define H_   2048
#define NH_  16
#define NG_  4
#define HD_  128
#define M_   (B_ * S_)
#define KVN_ (NG_ * HD_)

__device__ __align__(256) __half g_Qh[M_ * H_];
__device__ __align__(256) __half g_Kh[M_ * KVN_];
__device__ __align__(256) __half g_Vt[B_ * NG_ * HD_ * S_];   // [b][g][d][t]
__device__ __align__(256) __half g_Xh[M_ * H_];
__device__ __align__(256) __half g_Wqh[H_ * H_];
__device__ __align__(256) __half g_Wkh[KVN_ * H_];
__device__ __align__(256) __half g_Wvh[KVN_ * H_];

// ---------------------------------------------------------------------------
__device__ __forceinline__ uint32_t pkh2(float lo, float hi) {
    uint32_t d;
    asm("cvt.rn.f16x2.f32 %0, %1, %2;" : "=r"(d) : "f"(hi), "f"(lo));
    return d;
}
__device__ __forceinline__ uint32_t ex2h2(uint32_t x) {
    uint32_t d;
    asm("ex2.approx.f16x2 %0, %1;" : "=r"(d) : "r"(x));
    return d;
}
__device__ __forceinline__ uint32_t hadd2u(uint32_t a, uint32_t b) {
    uint32_t d;
    asm("add.f16x2 %0, %1, %2;" : "=r"(d) : "r"(a), "r"(b));
    return d;
}
__device__ __forceinline__ void mma16(float* d, const uint32_t* a, const uint32_t* b) {
    asm volatile(
        "mma.sync.aligned.m16n8k16.row.col.f32.f16.f16.f32 "
        "{%0,%1,%2,%3}, {%4,%5,%6,%7}, {%8,%9}, {%0,%1,%2,%3};"
        : "+f"(d[0]), "+f"(d[1]), "+f"(d[2]), "+f"(d[3])
        : "r"(a[0]), "r"(a[1]), "r"(a[2]), "r"(a[3]), "r"(b[0]), "r"(b[1]));
}
__device__ __forceinline__ void ldsm4(uint32_t& r0, uint32_t& r1,
                                      uint32_t& r2, uint32_t& r3, uint32_t addr) {
    asm volatile("ldmatrix.sync.aligned.m8n8.x4.shared.b16 {%0,%1,%2,%3}, [%4];"
                 : "=r"(r0), "=r"(r1), "=r"(r2), "=r"(r3) : "r"(addr));
}
__device__ __forceinline__ void cp16(uint32_t s, const void* g) {
    asm volatile("cp.async.cg.shared.global [%0], [%1], 16;\n" :: "r"(s), "l"(g));
}
__device__ __forceinline__ void cpcommit() { asm volatile("cp.async.commit_group;\n"); }
template <int N>
__device__ __forceinline__ void cpwait() { asm volatile("cp.async.wait_group %0;\n" :: "n"(N)); }
__device__ __forceinline__ uint32_t s2u(const void* p) {
    uint32_t a;
    asm("{.reg .u64 t; cvta.to.shared.u64 t, %1; cvt.u32.u64 %0, t;}" : "=r"(a) : "l"(p));
    return a;
}

// ---------------------------------------------------------------------------
// fused fp32 -> fp16 conversion of X, Wq, Wk, Wv (8 elems/thread)
// ---------------------------------------------------------------------------
#define CVT_XB   4096
#define CVT_WQB  (CVT_XB + 2048)
#define CVT_WKB  (CVT_WQB + 512)
#define CVT_NB   (CVT_WKB + 512)

__global__ __launch_bounds__(256) void cvt_all(
    const float4* __restrict__ X,  const float4* __restrict__ Wq,
    const float4* __restrict__ Wk, const float4* __restrict__ Wv,
    uint4* __restrict__ Xh, uint4* __restrict__ Wqh,
    uint4* __restrict__ Wkh, uint4* __restrict__ Wvh)
{
    int bid = blockIdx.x;
    const float4* src;
    uint4* dst;
    int base;
    if (bid < CVT_XB)       { src = X;  dst = Xh;  base = bid; }
    else if (bid < CVT_WQB) { src = Wq; dst = Wqh; base = bid - CVT_XB; }
    else if (bid < CVT_WKB) { src = Wk; dst = Wkh; base = bid - CVT_WQB; }
    else                    { src = Wv; dst = Wvh; base = bid - CVT_WKB; }
    int i = base * 256 + threadIdx.x;
    float4 a = src[2 * i], b = src[2 * i + 1];
    uint4 o;
    o.x = pkh2(a.x, a.y); o.y = pkh2(a.z, a.w);
    o.z = pkh2(b.x, b.y); o.w = pkh2(b.z, b.w);
    dst[i] = o;
}

// ---------------------------------------------------------------------------
// GEMM core: fp16 smem, LDSM frags, BK=64, 3-stage cp.async. (round-13)
// ---------------------------------------------------------------------------
#define GROWW 36
#define GTILE (128 * GROWW)
#define GSTAGE (2 * GTILE)
#define GSTAGES 3
#define GEMM_SMEM (GSTAGES * GSTAGE * 4)   // 110592 B

struct GemmAcc { float a[4][4][4]; };

__device__ __forceinline__ void gemm_mainloop(
    const __half* __restrict__ X, const __half* __restrict__ W,
    int bm, int bn, int K, uint32_t smB, GemmAcc& A)
{
    const int t = threadIdx.x;
    const int lane = t & 31;
    const int wid = t >> 5;
    const int wm = (wid & 1) * 64;
    const int wn = (wid >> 1) * 32;
    const int lm = lane >> 3, lr = lane & 7;
    const uint32_t aboff = (uint32_t)(((lm & 1) * 8 + lr) * 144 + (lm >> 1) * 16);
    const uint32_t bboff = (uint32_t)(((lm >> 1) * 8 + lr) * 144 + (lm & 1) * 16);

#pragma unroll
    for (int mt = 0; mt < 4; mt++)
#pragma unroll
        for (int nt = 0; nt < 4; nt++)
#pragma unroll
            for (int r = 0; r < 4; r++) A.a[mt][nt][r] = 0.f;

    const int NIT = K / 64;

    auto stage_load = [&](int slice, int buf) {
        const uint32_t sb = smB + (uint32_t)buf * (GSTAGE * 4);
        const int k0 = slice * 64;
#pragma unroll
        for (int i = 0; i < 4; i++) {
            int fi = t + i * 256;
            int row = fi >> 3, c = fi & 7;
            cp16(sb + (uint32_t)(row * GROWW + c * 4) * 4,
                 X + (size_t)(bm + row) * K + k0 + c * 8);
            cp16(sb + (uint32_t)(GTILE + row * GROWW + c * 4) * 4,
                 W + (size_t)(bn + row) * K + k0 + c * 8);
        }
    };

#pragma unroll
    for (int s = 0; s < GSTAGES - 1; s++) {
        stage_load(s, s);
        cpcommit();
    }

    for (int it = 0; it < NIT; it++) {
        cpwait<GSTAGES - 2>();
        __syncthreads();
        int pf = it + GSTAGES - 1;
        if (pf < NIT) stage_load(pf, pf % GSTAGES);
        cpcommit();

        const uint32_t sb = smB + (uint32_t)(it % GSTAGES) * (GSTAGE * 4);
        const uint32_t aB = sb + (uint32_t)wm * 144 + aboff;
        const uint32_t bB = sb + (uint32_t)GTILE * 4 + (uint32_t)wn * 144 + bboff;
#pragma unroll
        for (int ks = 0; ks < 4; ks++) {
            uint32_t a[4][4], b[4][2];
#pragma unroll
            for (int mt = 0; mt < 4; mt++)
                ldsm4(a[mt][0], a[mt][1], a[mt][2], a[mt][3],
                      aB + (uint32_t)(mt * 16 * 144 + ks * 32));
#pragma unroll
            for (int p = 0; p < 2; p++) {
                uint32_t b0, b1, b2, b3;
                ldsm4(b0, b1, b2, b3, bB + (uint32_t)(p * 16 * 144 + ks * 32));
                b[2 * p][0] = b0; b[2 * p][1] = b1;
                b[2 * p + 1][0] = b2; b[2 * p + 1][1] = b3;
            }
#pragma unroll
            for (int mt = 0; mt < 4; mt++)
#pragma unroll
                for (int nt = 0; nt < 4; nt++)
                    mma16(A.a[mt][nt], a[mt], b[nt]);
        }
    }
}

// Fused Q/K/V projections. blockIdx.x: [0,16) Q, [16,20) K, [20,24) V^T.
// V^T epilogue stages the tile transposed in smem for coalesced stores.
#define TTS 136   // transpose-stage stride in halves
__global__ __launch_bounds__(256, 2) void gemm_qkv(
    const __half* __restrict__ X,
    const __half* __restrict__ Wq, const __half* __restrict__ Wk,
    const __half* __restrict__ Wv,
    const float* __restrict__ bq, const float* __restrict__ bk,
    const float* __restrict__ bv,
    __half* __restrict__ Qout, __half* __restrict__ Kout,
    __half* __restrict__ Vt)
{
    extern __shared__ uint32_t gsm[];
    const int x = blockIdx.x;
    const int bm = blockIdx.y * 128;
    int mode, bn;
    const __half* W;
    const float* bias;
    if (x < 16)      { mode = 0; bn = x * 128;        W = Wq; bias = bq; }
    else if (x < 20) { mode = 1; bn = (x - 16) * 128; W = Wk; bias = bk; }
    else             { mode = 2; bn = (x - 20) * 128; W = Wv; bias = bv; }

    GemmAcc A;
    gemm_mainloop(X, W, bm, bn, H_, s2u(gsm), A);

    const int t = threadIdx.x;
    const int lane = t & 31;
    const int wid = t >> 5;
    const int wm = (wid & 1) * 64, wn = (wid >> 1) * 32;
    const int lg = lane >> 2, lt = lane & 3;

    if (mode == 2) {
        // stage transposed tile Tt[col][row] in smem, then coalesced stores
        __syncthreads();            // pipeline buffers are dead; reuse gsm
        __half* Tt = (__half*)gsm;  // [128 cols][TTS]
#pragma unroll
        for (int mt = 0; mt < 4; mt++) {
            int lr0 = wm + mt * 16 + lg;
#pragma unroll
            for (int nt = 0; nt < 4; nt++) {
                int lc = wn + nt * 8 + lt * 2;
                float2 bs = *(const float2*)&bias[bn + lc];
                Tt[lc * TTS + lr0]           = __float2half_rn(A.a[mt][nt][0] + bs.x);
                Tt[(lc + 1) * TTS + lr0]     = __float2half_rn(A.a[mt][nt][1] + bs.y);
                Tt[lc * TTS + lr0 + 8]       = __float2half_rn(A.a[mt][nt][2] + bs.x);
                Tt[(lc + 1) * TTS + lr0 + 8] = __float2half_rn(A.a[mt][nt][3] + bs.y);
            }
        }
        __syncthreads();
        const int bb = bm >> 11, tt0 = bm & 2047;
#pragma unroll
        for (int i = 0; i < 8; i++) {
            int fi = t + i * 256;           // 0..2047
            int c = fi >> 4, u = fi & 15;   // col 0..127, 8-half chunk 0..15
            int gcol = bn + c;
            int gg = gcol >> 7, d = gcol & 127;
            uint4 v = *(const uint4*)&Tt[c * TTS + u * 8];
            *(uint4*)&Vt[(size_t)(((bb * NG_ + gg) * HD_ + d)) * S_ + tt0 + u * 8] = v;
        }
    } else {
#pragma unroll
        for (int mt = 0; mt < 4; mt++) {
            int row = bm + wm + mt * 16 + lg;
#pragma unroll
            for (int nt = 0; nt < 4; nt++) {
                int col = bn + wn + nt * 8 + lt * 2;
                float2 bs = *(const float2*)&bias[col];
                uint32_t o0 = pkh2(A.a[mt][nt][0] + bs.x, A.a[mt][nt][1] + bs.y);
                uint32_t o1 = pkh2(A.a[mt][nt][2] + bs.x, A.a[mt][nt][3] + bs.y);
                __half* C = (mode == 0) ? Qout : Kout;
                int N = (mode == 0) ? H_ : KVN_;
                *(uint32_t*)&C[(size_t)row * N + col] = o0;
                *(uint32_t*)&C[(size_t)(row + 8) * N + col] = o1;
            }
        }
    }
}

// ---------------------------------------------------------------------------
// Flash attention, key-split warps + smem mask + lazy O-rescale (round-13).
// ---------------------------------------------------------------------------
#define ABM 64
#define ABN 64
#define KSTRW 68
#define VSTRW 36
#define QF_OFF 0
#define QF_WORDS (4 * 8 * 32 * 4)              // 4096
#define KV_OFF QF_WORDS
#define MSK_OFF (ABN * KSTRW + HD_ * VSTRW)    // 8960 words into a buffer
#define KVBUF (MSK_OFF + ABN)                  // 9024 words
#define ATT_SMEM ((KV_OFF + 2 * KVBUF) * 4)    // 88576 B
#define MRG_STR 132
#define MRG_PAIR (16 * MRG_STR + 64)           // 2176 words per pair

__global__ __launch_bounds__(256, 2) void attn_f16(
    const __half* __restrict__ Q, const __half* __restrict__ K,
    const __half* __restrict__ Vt, const int* __restrict__ amask,
    float* __restrict__ out)
{
    extern __shared__ uint32_t smu[];
    uint32_t* Qf = smu + QF_OFF;
    const uint32_t smB = s2u(smu);

    const int b = blockIdx.z;
    const int h = blockIdx.y;
    const int g = h >> 2;
    const int q0 = blockIdx.x * ABM;
    const int t = threadIdx.x;
    const int lane = t & 31;
    const int wid = t >> 5;
    const int qp = wid >> 1;
    const int half = wid & 1;
    const int lg = lane >> 2;
    const int lt = lane & 3;
    const int lm = lane >> 3, lr = lane & 7;
    const uint32_t kboff = (uint32_t)(((lm >> 1) * 8 + lr) * (KSTRW * 4) + (lm & 1) * 16)
                         + (uint32_t)(half * 32 * KSTRW * 4);
    const uint32_t vboff = (uint32_t)(((lm >> 1) * 8 + lr) * (VSTRW * 4) + (lm & 1) * 16)
                         + (uint32_t)(half * 64);

    const __half* Kbase  = K + (size_t)(b * S_) * KVN_ + g * HD_;
    const __half* Vtbase = Vt + ((size_t)(b * NG_ + g) * HD_) * S_;
    const int* mrow = amask + b * S_;
    const float scl2 = 0.08838834764831845f * 1.4426950408889634f;

    auto tile_load = [&](int kt, int buf) {
        const uint32_t kb = smB + (uint32_t)(KV_OFF + buf * KVBUF) * 4;
        const uint32_t vb = kb + (uint32_t)(ABN * KSTRW) * 4;
        const int kr0 = kt * ABN;
#pragma unroll
        for (int i = 0; i < 4; i++) {
            int fi = t + i * 256;
            int krow = fi >> 4, kc = fi & 15;
            cp16(kb + (uint32_t)(krow * KSTRW + kc * 4) * 4,
                 Kbase + (size_t)(kr0 + krow) * KVN_ + kc * 8);
            int vrow = fi >> 3, vc = fi & 7;
            cp16(vb + (uint32_t)(vrow * VSTRW + vc * 4) * 4,
                 Vtbase + (size_t)vrow * S_ + kr0 + vc * 8);
        }
        if (t < ABN) {
            float* Msm = (float*)(smu + KV_OFF + buf * KVBUF + MSK_OFF);
            Msm[t] = mrow[kr0 + t] ? 0.f : -3.4028234663852886e38f;
        }
    };

    tile_load(0, 0);
    cpcommit();

    const __half* Qbase = Q + ((size_t)(b * S_ + q0)) * H_ + h * HD_;
#pragma unroll
    for (int i = 0; i < 4; i++) {
        int fi = t + i * 256;
        int row = fi >> 4, c8 = fi & 15;
        uint4 u = *(const uint4*)(Qbase + (size_t)row * H_ + c8 * 8);
        int w = row >> 4, rr = row & 15;
        int lgw = rr & 7, rh = rr >> 3;
        int ks = c8 >> 1, hi = c8 & 1;
        int reg = rh + 2 * hi;
        uint32_t* p = &Qf[(((w * 8 + ks) * 32) + lgw * 4) * 4 + reg];
        p[0] = u.x; p[4] = u.y; p[8] = u.z; p[12] = u.w;
    }

    float m_run[2] = { -FLT_MAX, -FLT_MAX };
    float l_run[2] = { 0.f, 0.f };
    float Oa[16][4];
#pragma unroll
    for (int nt = 0; nt < 16; nt++)
#pragma unroll
        for (int r = 0; r < 4; r++) Oa[nt][r] = 0.f;

    const int NKT = S_ / ABN;
    for (int kt = 0; kt < NKT; kt++) {
        const int buf = kt & 1;
        cpwait<0>();
        __syncthreads();
        if (kt + 1 < NKT) tile_load(kt + 1, buf ^ 1);
        cpcommit();

        const uint32_t kB = smB + (uint32_t)(KV_OFF + buf * KVBUF) * 4 + kboff;
        const uint32_t vB = smB + (uint32_t)(KV_OFF + buf * KVBUF + ABN * KSTRW) * 4 + vboff;
        const float* Msm = (const float*)(smu + KV_OFF + buf * KVBUF + MSK_OFF);

        float sc[4][4];
#pragma unroll
        for (int nt = 0; nt < 4; nt++)
#pragma unroll
            for (int r = 0; r < 4; r++) sc[nt][r] = 0.f;

#pragma unroll
        for (int ks = 0; ks < 8; ks++) {
            uint4 av = *(const uint4*)&Qf[((qp * 8 + ks) * 32 + lane) * 4];
            uint32_t a[4] = { av.x, av.y, av.z, av.w };
#pragma unroll
            for (int p = 0; p < 2; p++) {
                uint32_t b0, b1, b2, b3;
                ldsm4(b0, b1, b2, b3,
                      kB + (uint32_t)(p * 16 * KSTRW * 4 + ks * 32));
                uint32_t bb0[2] = { b0, b1 }, bb1[2] = { b2, b3 };
                mma16(sc[2 * p], a, bb0);
                mma16(sc[2 * p + 1], a, bb1);
            }
        }

#pragma unroll
        for (int nt = 0; nt < 4; nt++) {
            float2 mm = *(const float2*)&Msm[half * 32 + nt * 8 + lt * 2];
            sc[nt][0] = sc[nt][0] * scl2 + mm.x;
            sc[nt][1] = sc[nt][1] * scl2 + mm.y;
            sc[nt][2] = sc[nt][2] * scl2 + mm.x;
            sc[nt][3] = sc[nt][3] * scl2 + mm.y;
        }

        float mloc[2] = { -FLT_MAX, -FLT_MAX };
#pragma unroll
        for (int nt = 0; nt < 4; nt++) {
            mloc[0] = fmaxf(mloc[0], fmaxf(sc[nt][0], sc[nt][1]));
            mloc[1] = fmaxf(mloc[1], fmaxf(sc[nt][2], sc[nt][3]));
        }
#pragma unroll
        for (int off = 1; off <= 2; off <<= 1) {
            mloc[0] = fmaxf(mloc[0], __shfl_xor_sync(0xffffffffu, mloc[0], off));
            mloc[1] = fmaxf(mloc[1], __shfl_xor_sync(0xffffffffu, mloc[1], off));
        }
        bool need = (mloc[0] > m_run[0]) || (mloc[1] > m_run[1]);
        if (__any_sync(0xffffffffu, need)) {
            float mnew[2], alpha[2];
#pragma unroll
            for (int r = 0; r < 2; r++) {
                mnew[r] = fmaxf(m_run[r], mloc[r]);
                alpha[r] = exp2f(m_run[r] - mnew[r]);
                m_run[r] = mnew[r];
            }
            l_run[0] *= alpha[0];
            l_run[1] *= alpha[1];
#pragma unroll
            for (int nt = 0; nt < 16; nt++) {
                Oa[nt][0] *= alpha[0];
                Oa[nt][1] *= alpha[0];
                Oa[nt][2] *= alpha[1];
                Oa[nt][3] *= alpha[1];
            }
        }

        uint32_t ph_lo[4], ph_hi[4];
        uint32_t acc_lo = 0u, acc_hi = 0u;
#pragma unroll
        for (int nt = 0; nt < 4; nt++) {
            ph_lo[nt] = ex2h2(pkh2(sc[nt][0] - m_run[0], sc[nt][1] - m_run[0]));
            ph_hi[nt] = ex2h2(pkh2(sc[nt][2] - m_run[1], sc[nt][3] - m_run[1]));
            acc_lo = hadd2u(acc_lo, ph_lo[nt]);
            acc_hi = hadd2u(acc_hi, ph_hi[nt]);
        }
        __half2 h0 = *reinterpret_cast<__half2*>(&acc_lo);
        __half2 h1 = *reinterpret_cast<__half2*>(&acc_hi);
        float rs[2] = { __low2float(h0) + __high2float(h0),
                        __low2float(h1) + __high2float(h1) };
#pragma unroll
        for (int off = 1; off <= 2; off <<= 1) {
            rs[0] += __shfl_xor_sync(0xffffffffu, rs[0], off);
            rs[1] += __shfl_xor_sync(0xffffffffu, rs[1], off);
        }
        l_run[0] += rs[0];
        l_run[1] += rs[1];

#pragma unroll
        for (int ks = 0; ks < 2; ks++) {
            uint32_t a[4] = { ph_lo[2 * ks], ph_hi[2 * ks],
                              ph_lo[2 * ks + 1], ph_hi[2 * ks + 1] };
#pragma unroll
            for (int p = 0; p < 8; p++) {
                uint32_t b0, b1, b2, b3;
                ldsm4(b0, b1, b2, b3,
                      vB + (uint32_t)(p * 16 * VSTRW * 4 + ks * 32));
                uint32_t bb0[2] = { b0, b1 }, bb1[2] = { b2, b3 };
                mma16(Oa[2 * p], a, bb0);
                mma16(Oa[2 * p + 1], a, bb1);
            }
        }
    }

    // ---- merge key halves (reuse dead K/V smem) -----------------------------
    __syncthreads();
    float* Mrg = (float*)(smu + KV_OFF);
    float* pbase = Mrg + qp * MRG_PAIR;
    if (half == 1) {
#pragma unroll
        for (int nt = 0; nt < 16; nt++) {
            int col = nt * 8 + lt * 2;
            *(float2*)&pbase[lg * MRG_STR + col]       = { Oa[nt][0], Oa[nt][1] };
            *(float2*)&pbase[(lg + 8) * MRG_STR + col] = { Oa[nt][2], Oa[nt][3] };
        }
        if (lt == 0) {
            *(float2*)&pbase[16 * MRG_STR + lg * 2]       = { m_run[0], l_run[0] };
            *(float2*)&pbase[16 * MRG_STR + (lg + 8) * 2] = { m_run[1], l_run[1] };
        }
    }
    __syncthreads();
    if (half == 0) {
        float2 mlB0 = *(float2*)&pbase[16 * MRG_STR + lg * 2];
        float2 mlB1 = *(float2*)&pbase[16 * MRG_STR + (lg + 8) * 2];
        float m0 = fmaxf(m_run[0], mlB0.x);
        float m1 = fmaxf(m_run[1], mlB1.x);
        float fA0 = exp2f(m_run[0] - m0), fB0 = exp2f(mlB0.x - m0);
        float fA1 = exp2f(m_run[1] - m1), fB1 = exp2f(mlB1.x - m1);
        float inv0 = 1.f / (l_run[0] * fA0 + mlB0.y * fB0);
        float inv1 = 1.f / (l_run[1] * fA1 + mlB1.y * fB1);

        int row = q0 + qp * 16 + lg;
        float* ob0 = out + ((size_t)(b * S_ + row)) * H_ + h * HD_;
        float* ob1 = out + ((size_t)(b * S_ + row + 8)) * H_ + h * HD_;
#pragma unroll
        for (int nt = 0; nt < 16; nt++) {
            int col = nt * 8 + lt * 2;
            float2 OB0 = *(float2*)&pbase[lg * MRG_STR + col];
            float2 OB1 = *(float2*)&pbase[(lg + 8) * MRG_STR + col];
            float2 o0 = { (Oa[nt][0] * fA0 + OB0.x * fB0) * inv0,
                          (Oa[nt][1] * fA0 + OB0.y * fB0) * inv0 };
            float2 o1 = { (Oa[nt][2] * fA1 + OB1.x * fB1) * inv1,
                          (Oa[nt][3] * fA1 + OB1.y * fB1) * inv1 };
            *(float2*)&ob0[col] = o0;
            *(float2*)&ob1[col] = o1;
        }
    }
}

// ---------------------------------------------------------------------------
extern "C" void kernel_launch(void* const* d_in, const int* in_sizes, int n_in,
                              void* d_out, int out_size)
{
    const float* X     = (const float*)d_in[0];
    const int*   amask = (const int*)  d_in[1];
    const float* Wq    = (const float*)d_in[2];
    const float* bq    = (const float*)d_in[3];
    const float* Wk    = (const float*)d_in[4];
    const float* bk    = (const float*)d_in[5];
    const float* Wv    = (const float*)d_in[6];
    const float* bv    = (const float*)d_in[7];
    float* out = (float*)d_out;

    __half *Qp, *Kp, *Vp, *Xh, *Wqh, *Wkh, *Wvh;
    cudaGetSymbolAddress((void**)&Qp, g_Qh);
    cudaGetSymbolAddress((void**)&Kp, g_Kh);
    cudaGetSymbolAddress((void**)&Vp, g_Vt);
    cudaGetSymbolAddress((void**)&Xh, g_Xh);
    cudaGetSymbolAddress((void**)&Wqh, g_Wqh);
    cudaGetSymbolAddress((void**)&Wkh, g_Wkh);
    cudaGetSymbolAddress((void**)&Wvh, g_Wvh);

    cvt_all<<<CVT_NB, 256>>>((const float4*)X, (const float4*)Wq,
                             (const float4*)Wk, (const float4*)Wv,
                             (uint4*)Xh, (uint4*)Wqh, (uint4*)Wkh, (uint4*)Wvh);

    cudaFuncSetAttribute(gemm_qkv,
                         cudaFuncAttributeMaxDynamicSharedMemorySize, GEMM_SMEM);
    gemm_qkv<<<dim3(24, M_ / 128), 256, GEMM_SMEM>>>(
        Xh, Wqh, Wkh, Wvh, bq, bk, bv, Qp, Kp, Vp);

    cudaFuncSetAttribute(attn_f16,
                         cudaFuncAttributeMaxDynamicSharedMemorySize, ATT_SMEM);
    attn_f16<<<dim3(S_ / ABM, NH_, B_), 256, ATT_SMEM>>>(Qp, Kp, Vp, amask, out);
}

// round 17
// speedup vs baseline: 1.1346x; 1.0009x over previous
#include <cuda_runtime.h>
#include <cuda_fp16.h>
#include <cfloat>
#include <cstdint>

#define B_   2
#define S_   2048
#define H_   2048
#define NH_  16
#define NG_  4
#define HD_  128
#define M_   (B_ * S_)
#define KVN_ (NG_ * HD_)

__device__ __align__(256) __half g_Qh[M_ * H_];
__device__ __align__(256) __half g_Kh[M_ * KVN_];
__device__ __align__(256) __half g_Vt[B_ * NG_ * HD_ * S_];   // [b][g][d][t]
__device__ __align__(256) __half g_Xh[M_ * H_];
__device__ __align__(256) __half g_Wqh[H_ * H_];
__device__ __align__(256) __half g_Wkh[KVN_ * H_];
__device__ __align__(256) __half g_Wvh[KVN_ * H_];

// ---------------------------------------------------------------------------
__device__ __forceinline__ uint32_t pkh2(float lo, float hi) {
    uint32_t d;
    asm("cvt.rn.f16x2.f32 %0, %1, %2;" : "=r"(d) : "f"(hi), "f"(lo));
    return d;
}
__device__ __forceinline__ uint32_t ex2h2(uint32_t x) {
    uint32_t d;
    asm("ex2.approx.f16x2 %0, %1;" : "=r"(d) : "r"(x));
    return d;
}
__device__ __forceinline__ uint32_t hadd2u(uint32_t a, uint32_t b) {
    uint32_t d;
    asm("add.f16x2 %0, %1, %2;" : "=r"(d) : "r"(a), "r"(b));
    return d;
}
__device__ __forceinline__ void mma16(float* d, const uint32_t* a, const uint32_t* b) {
    asm volatile(
        "mma.sync.aligned.m16n8k16.row.col.f32.f16.f16.f32 "
        "{%0,%1,%2,%3}, {%4,%5,%6,%7}, {%8,%9}, {%0,%1,%2,%3};"
        : "+f"(d[0]), "+f"(d[1]), "+f"(d[2]), "+f"(d[3])
        : "r"(a[0]), "r"(a[1]), "r"(a[2]), "r"(a[3]), "r"(b[0]), "r"(b[1]));
}
__device__ __forceinline__ void ldsm4(uint32_t& r0, uint32_t& r1,
                                      uint32_t& r2, uint32_t& r3, uint32_t addr) {
    asm volatile("ldmatrix.sync.aligned.m8n8.x4.shared.b16 {%0,%1,%2,%3}, [%4];"
                 : "=r"(r0), "=r"(r1), "=r"(r2), "=r"(r3) : "r"(addr));
}
__device__ __forceinline__ void cp16(uint32_t s, const void* g) {
    asm volatile("cp.async.cg.shared.global [%0], [%1], 16;\n" :: "r"(s), "l"(g));
}
__device__ __forceinline__ void cpcommit() { asm volatile("cp.async.commit_group;\n"); }
template <int N>
__device__ __forceinline__ void cpwait() { asm volatile("cp.async.wait_group %0;\n" :: "n"(N)); }
__device__ __forceinline__ uint32_t s2u(const void* p) {
    uint32_t a;
    asm("{.reg .u64 t; cvta.to.shared.u64 t, %1; cvt.u32.u64 %0, t;}" : "=r"(a) : "l"(p));
    return a;
}

// ---------------------------------------------------------------------------
// fused fp32 -> fp16 conversion of X, Wq, Wk, Wv (16 elems/thread, MLP=4)
// ---------------------------------------------------------------------------
#define CVT_XB   2048
#define CVT_WQB  (CVT_XB + 1024)
#define CVT_WKB  (CVT_WQB + 256)
#define CVT_NB   (CVT_WKB + 256)

__global__ __launch_bounds__(256) void cvt_all(
    const float4* __restrict__ X,  const float4* __restrict__ Wq,
    const float4* __restrict__ Wk, const float4* __restrict__ Wv,
    uint4* __restrict__ Xh, uint4* __restrict__ Wqh,
    uint4* __restrict__ Wkh, uint4* __restrict__ Wvh)
{
    int bid = blockIdx.x;
    const float4* src;
    uint4* dst;
    int base;
    if (bid < CVT_XB)       { src = X;  dst = Xh;  base = bid; }
    else if (bid < CVT_WQB) { src = Wq; dst = Wqh; base = bid - CVT_XB; }
    else if (bid < CVT_WKB) { src = Wk; dst = Wkh; base = bid - CVT_WQB; }
    else                    { src = Wv; dst = Wvh; base = bid - CVT_WKB; }
    int i = base * 256 + threadIdx.x;
    float4 a = src[4 * i], b = src[4 * i + 1];
    float4 c = src[4 * i + 2], d = src[4 * i + 3];
    uint4 o0, o1;
    o0.x = pkh2(a.x, a.y); o0.y = pkh2(a.z, a.w);
    o0.z = pkh2(b.x, b.y); o0.w = pkh2(b.z, b.w);
    o1.x = pkh2(c.x, c.y); o1.y = pkh2(c.z, c.w);
    o1.z = pkh2(d.x, d.y); o1.w = pkh2(d.z, d.w);
    dst[2 * i] = o0;
    dst[2 * i + 1] = o1;
}

// ---------------------------------------------------------------------------
// GEMM core: fp16 smem, LDSM frags, BK=64, 3-stage cp.async.
// ---------------------------------------------------------------------------
#define GROWW 36
#define GTILE (128 * GROWW)
#define GSTAGE (2 * GTILE)
#define GSTAGES 3
#define GEMM_SMEM (GSTAGES * GSTAGE * 4)   // 110592 B

struct GemmAcc { float a[4][4][4]; };

__device__ __forceinline__ void gemm_mainloop(
    const __half* __restrict__ X, const __half* __restrict__ W,
    int bm, int bn, int K, uint32_t smB, GemmAcc& A)
{
    const int t = threadIdx.x;
    const int lane = t & 31;
    const int wid = t >> 5;
    const int wm = (wid & 1) * 64;
    const int wn = (wid >> 1) * 32;
    const int lm = lane >> 3, lr = lane & 7;
    const uint32_t aboff = (uint32_t)(((lm & 1) * 8 + lr) * 144 + (lm >> 1) * 16);
    const uint32_t bboff = (uint32_t)(((lm >> 1) * 8 + lr) * 144 + (lm & 1) * 16);

#pragma unroll
    for (int mt = 0; mt < 4; mt++)
#pragma unroll
        for (int nt = 0; nt < 4; nt++)
#pragma unroll
            for (int r = 0; r < 4; r++) A.a[mt][nt][r] = 0.f;

    const int NIT = K / 64;

    auto stage_load = [&](int slice, int buf) {
        const uint32_t sb = smB + (uint32_t)buf * (GSTAGE * 4);
        const int k0 = slice * 64;
#pragma unroll
        for (int i = 0; i < 4; i++) {
            int fi = t + i * 256;
            int row = fi >> 3, c = fi & 7;
            cp16(sb + (uint32_t)(row * GROWW + c * 4) * 4,
                 X + (size_t)(bm + row) * K + k0 + c * 8);
            cp16(sb + (uint32_t)(GTILE + row * GROWW + c * 4) * 4,
                 W + (size_t)(bn + row) * K + k0 + c * 8);
        }
    };

#pragma unroll
    for (int s = 0; s < GSTAGES - 1; s++) {
        stage_load(s, s);
        cpcommit();
    }

    for (int it = 0; it < NIT; it++) {
        cpwait<GSTAGES - 2>();
        __syncthreads();
        int pf = it + GSTAGES - 1;
        if (pf < NIT) stage_load(pf, pf % GSTAGES);
        cpcommit();

        const uint32_t sb = smB + (uint32_t)(it % GSTAGES) * (GSTAGE * 4);
        const uint32_t aB = sb + (uint32_t)wm * 144 + aboff;
        const uint32_t bB = sb + (uint32_t)GTILE * 4 + (uint32_t)wn * 144 + bboff;
#pragma unroll
        for (int ks = 0; ks < 4; ks++) {
            uint32_t a[4][4], b[4][2];
#pragma unroll
            for (int mt = 0; mt < 4; mt++)
                ldsm4(a[mt][0], a[mt][1], a[mt][2], a[mt][3],
                      aB + (uint32_t)(mt * 16 * 144 + ks * 32));
#pragma unroll
            for (int p = 0; p < 2; p++) {
                uint32_t b0, b1, b2, b3;
                ldsm4(b0, b1, b2, b3, bB + (uint32_t)(p * 16 * 144 + ks * 32));
                b[2 * p][0] = b0; b[2 * p][1] = b1;
                b[2 * p + 1][0] = b2; b[2 * p + 1][1] = b3;
            }
#pragma unroll
            for (int mt = 0; mt < 4; mt++)
#pragma unroll
                for (int nt = 0; nt < 4; nt++)
                    mma16(A.a[mt][nt], a[mt], b[nt]);
        }
    }
}

// Fused Q/K/V projections. blockIdx.x: [0,16) Q, [16,20) K, [20,24) V^T.
// V^T epilogue stages the tile transposed in smem for coalesced stores.
#define TTS 136   // transpose-stage stride in halves
__global__ __launch_bounds__(256, 2) void gemm_qkv(
    const __half* __restrict__ X,
    const __half* __restrict__ Wq, const __half* __restrict__ Wk,
    const __half* __restrict__ Wv,
    const float* __restrict__ bq, const float* __restrict__ bk,
    const float* __restrict__ bv,
    __half* __restrict__ Qout, __half* __restrict__ Kout,
    __half* __restrict__ Vt)
{
    extern __shared__ uint32_t gsm[];
    const int x = blockIdx.x;
    const int bm = blockIdx.y * 128;
    int mode, bn;
    const __half* W;
    const float* bias;
    if (x < 16)      { mode = 0; bn = x * 128;        W = Wq; bias = bq; }
    else if (x < 20) { mode = 1; bn = (x - 16) * 128; W = Wk; bias = bk; }
    else             { mode = 2; bn = (x - 20) * 128; W = Wv; bias = bv; }

    GemmAcc A;
    gemm_mainloop(X, W, bm, bn, H_, s2u(gsm), A);

    const int t = threadIdx.x;
    const int lane = t & 31;
    const int wid = t >> 5;
    const int wm = (wid & 1) * 64, wn = (wid >> 1) * 32;
    const int lg = lane >> 2, lt = lane & 3;

    if (mode == 2) {
        __syncthreads();            // pipeline buffers are dead; reuse gsm
        __half* Tt = (__half*)gsm;  // [128 cols][TTS]
#pragma unroll
        for (int mt = 0; mt < 4; mt++) {
            int lr0 = wm + mt * 16 + lg;
#pragma unroll
            for (int nt = 0; nt < 4; nt++) {
                int lc = wn + nt * 8 + lt * 2;
                float2 bs = *(const float2*)&bias[bn + lc];
                Tt[lc * TTS + lr0]           = __float2half_rn(A.a[mt][nt][0] + bs.x);
                Tt[(lc + 1) * TTS + lr0]     = __float2half_rn(A.a[mt][nt][1] + bs.y);
                Tt[lc * TTS + lr0 + 8]       = __float2half_rn(A.a[mt][nt][2] + bs.x);
                Tt[(lc + 1) * TTS + lr0 + 8] = __float2half_rn(A.a[mt][nt][3] + bs.y);
            }
        }
        __syncthreads();
        const int bb = bm >> 11, tt0 = bm & 2047;
#pragma unroll
        for (int i = 0; i < 8; i++) {
            int fi = t + i * 256;
            int c = fi >> 4, u = fi & 15;
            int gcol = bn + c;
            int gg = gcol >> 7, d = gcol & 127;
            uint4 v = *(const uint4*)&Tt[c * TTS + u * 8];
            *(uint4*)&Vt[(size_t)(((bb * NG_ + gg) * HD_ + d)) * S_ + tt0 + u * 8] = v;
        }
    } else {
#pragma unroll
        for (int mt = 0; mt < 4; mt++) {
            int row = bm + wm + mt * 16 + lg;
#pragma unroll
            for (int nt = 0; nt < 4; nt++) {
                int col = bn + wn + nt * 8 + lt * 2;
                float2 bs = *(const float2*)&bias[col];
                uint32_t o0 = pkh2(A.a[mt][nt][0] + bs.x, A.a[mt][nt][1] + bs.y);
                uint32_t o1 = pkh2(A.a[mt][nt][2] + bs.x, A.a[mt][nt][3] + bs.y);
                __half* C = (mode == 0) ? Qout : Kout;
                int N = (mode == 0) ? H_ : KVN_;
                *(uint32_t*)&C[(size_t)row * N + col] = o0;
                *(uint32_t*)&C[(size_t)(row + 8) * N + col] = o1;
            }
        }
    }
}

// ---------------------------------------------------------------------------
// Flash attention, key-split warps + smem mask + lazy O-rescale (round-13).
// ---------------------------------------------------------------------------
#define ABM 64
#define ABN 64
#define KSTRW 68
#define VSTRW 36
#define QF_OFF 0
#define QF_WORDS (4 * 8 * 32 * 4)              // 4096
#define KV_OFF QF_WORDS
#define MSK_OFF (ABN * KSTRW + HD_ * VSTRW)    // 8960 words into a buffer
#define KVBUF (MSK_OFF + ABN)                  // 9024 words
#define ATT_SMEM ((KV_OFF + 2 * KVBUF) * 4)    // 88576 B
#define MRG_STR 132
#define MRG_PAIR (16 * MRG_STR + 64)           // 2176 words per pair

__global__ __launch_bounds__(256, 2) void attn_f16(
    const __half* __restrict__ Q, const __half* __restrict__ K,
    const __half* __restrict__ Vt, const int* __restrict__ amask,
    float* __restrict__ out)
{
    extern __shared__ uint32_t smu[];
    uint32_t* Qf = smu + QF_OFF;
    const uint32_t smB = s2u(smu);

    const int b = blockIdx.z;
    const int h = blockIdx.y;
    const int g = h >> 2;
    const int q0 = blockIdx.x * ABM;
    const int t = threadIdx.x;
    const int lane = t & 31;
    const int wid = t >> 5;
    const int qp = wid >> 1;
    const int half = wid & 1;
    const int lg = lane >> 2;
    const int lt = lane & 3;
    const int lm = lane >> 3, lr = lane & 7;
    const uint32_t kboff = (uint32_t)(((lm >> 1) * 8 + lr) * (KSTRW * 4) + (lm & 1) * 16)
                         + (uint32_t)(half * 32 * KSTRW * 4);
    const uint32_t vboff = (uint32_t)(((lm >> 1) * 8 + lr) * (VSTRW * 4) + (lm & 1) * 16)
                         + (uint32_t)(half * 64);

    const __half* Kbase  = K + (size_t)(b * S_) * KVN_ + g * HD_;
    const __half* Vtbase = Vt + ((size_t)(b * NG_ + g) * HD_) * S_;
    const int* mrow = amask + b * S_;
    const float scl2 = 0.08838834764831845f * 1.4426950408889634f;

    auto tile_load = [&](int kt, int buf) {
        const uint32_t kb = smB + (uint32_t)(KV_OFF + buf * KVBUF) * 4;
        const uint32_t vb = kb + (uint32_t)(ABN * KSTRW) * 4;
        const int kr0 = kt * ABN;
#pragma unroll
        for (int i = 0; i < 4; i++) {
            int fi = t + i * 256;
            int krow = fi >> 4, kc = fi & 15;
            cp16(kb + (uint32_t)(krow * KSTRW + kc * 4) * 4,
                 Kbase + (size_t)(kr0 + krow) * KVN_ + kc * 8);
            int vrow = fi >> 3, vc = fi & 7;
            cp16(vb + (uint32_t)(vrow * VSTRW + vc * 4) * 4,
                 Vtbase + (size_t)vrow * S_ + kr0 + vc * 8);
        }
        if (t < ABN) {
            float* Msm = (float*)(smu + KV_OFF + buf * KVBUF + MSK_OFF);
            Msm[t] = mrow[kr0 + t] ? 0.f : -3.4028234663852886e38f;
        }
    };

    tile_load(0, 0);
    cpcommit();

    const __half* Qbase = Q + ((size_t)(b * S_ + q0)) * H_ + h * HD_;
#pragma unroll
    for (int i = 0; i < 4; i++) {
        int fi = t + i * 256;
        int row = fi >> 4, c8 = fi & 15;
        uint4 u = *(const uint4*)(Qbase + (size_t)row * H_ + c8 * 8);
        int w = row >> 4, rr = row & 15;
        int lgw = rr & 7, rh = rr >> 3;
        int ks = c8 >> 1, hi = c8 & 1;
        int reg = rh + 2 * hi;
        uint32_t* p = &Qf[(((w * 8 + ks) * 32) + lgw * 4) * 4 + reg];
        p[0] = u.x; p[4] = u.y; p[8] = u.z; p[12] = u.w;
    }

    float m_run[2] = { -FLT_MAX, -FLT_MAX };
    float l_run[2] = { 0.f, 0.f };
    float Oa[16][4];
#pragma unroll
    for (int nt = 0; nt < 16; nt++)
#pragma unroll
        for (int r = 0; r < 4; r++) Oa[nt][r] = 0.f;

    const int NKT = S_ / ABN;
    for (int kt = 0; kt < NKT; kt++) {
        const int buf = kt & 1;
        cpwait<0>();
        __syncthreads();
        if (kt + 1 < NKT) tile_load(kt + 1, buf ^ 1);
        cpcommit();

        const uint32_t kB = smB + (uint32_t)(KV_OFF + buf * KVBUF) * 4 + kboff;
        const uint32_t vB = smB + (uint32_t)(KV_OFF + buf * KVBUF + ABN * KSTRW) * 4 + vboff;
        const float* Msm = (const float*)(smu + KV_OFF + buf * KVBUF + MSK_OFF);

        float sc[4][4];
#pragma unroll
        for (int nt = 0; nt < 4; nt++)
#pragma unroll
            for (int r = 0; r < 4; r++) sc[nt][r] = 0.f;

#pragma unroll
        for (int ks = 0; ks < 8; ks++) {
            uint4 av = *(const uint4*)&Qf[((qp * 8 + ks) * 32 + lane) * 4];
            uint32_t a[4] = { av.x, av.y, av.z, av.w };
#pragma unroll
            for (int p = 0; p < 2; p++) {
                uint32_t b0, b1, b2, b3;
                ldsm4(b0, b1, b2, b3,
                      kB + (uint32_t)(p * 16 * KSTRW * 4 + ks * 32));
                uint32_t bb0[2] = { b0, b1 }, bb1[2] = { b2, b3 };
                mma16(sc[2 * p], a, bb0);
                mma16(sc[2 * p + 1], a, bb1);
            }
        }

#pragma unroll
        for (int nt = 0; nt < 4; nt++) {
            float2 mm = *(const float2*)&Msm[half * 32 + nt * 8 + lt * 2];
            sc[nt][0] = sc[nt][0] * scl2 + mm.x;
            sc[nt][1] = sc[nt][1] * scl2 + mm.y;
            sc[nt][2] = sc[nt][2] * scl2 + mm.x;
            sc[nt][3] = sc[nt][3] * scl2 + mm.y;
        }

        float mloc[2] = { -FLT_MAX, -FLT_MAX };
#pragma unroll
        for (int nt = 0; nt < 4; nt++) {
            mloc[0] = fmaxf(mloc[0], fmaxf(sc[nt][0], sc[nt][1]));
            mloc[1] = fmaxf(mloc[1], fmaxf(sc[nt][2], sc[nt][3]));
        }
#pragma unroll
        for (int off = 1; off <= 2; off <<= 1) {
            mloc[0] = fmaxf(mloc[0], __shfl_xor_sync(0xffffffffu, mloc[0], off));
            mloc[1] = fmaxf(mloc[1], __shfl_xor_sync(0xffffffffu, mloc[1], off));
        }
        bool need = (mloc[0] > m_run[0]) || (mloc[1] > m_run[1]);
        if (__any_sync(0xffffffffu, need)) {
            float mnew[2], alpha[2];
#pragma unroll
            for (int r = 0; r < 2; r++) {
                mnew[r] = fmaxf(m_run[r], mloc[r]);
                alpha[r] = exp2f(m_run[r] - mnew[r]);
                m_run[r] = mnew[r];
            }
            l_run[0] *= alpha[0];
            l_run[1] *= alpha[1];
#pragma unroll
            for (int nt = 0; nt < 16; nt++) {
                Oa[nt][0] *= alpha[0];
                Oa[nt][1] *= alpha[0];
                Oa[nt][2] *= alpha[1];
                Oa[nt][3] *= alpha[1];
            }
        }

        uint32_t ph_lo[4], ph_hi[4];
        uint32_t acc_lo = 0u, acc_hi = 0u;
#pragma unroll
        for (int nt = 0; nt < 4; nt++) {
            ph_lo[nt] = ex2h2(pkh2(sc[nt][0] - m_run[0], sc[nt][1] - m_run[0]));
            ph_hi[nt] = ex2h2(pkh2(sc[nt][2] - m_run[1], sc[nt][3] - m_run[1]));
            acc_lo = hadd2u(acc_lo, ph_lo[nt]);
            acc_hi = hadd2u(acc_hi, ph_hi[nt]);
        }
        __half2 h0 = *reinterpret_cast<__half2*>(&acc_lo);
        __half2 h1 = *reinterpret_cast<__half2*>(&acc_hi);
        float rs[2] = { __low2float(h0) + __high2float(h0),
                        __low2float(h1) + __high2float(h1) };
#pragma unroll
        for (int off = 1; off <= 2; off <<= 1) {
            rs[0] += __shfl_xor_sync(0xffffffffu, rs[0], off);
            rs[1] += __shfl_xor_sync(0xffffffffu, rs[1], off);
        }
        l_run[0] += rs[0];
        l_run[1] += rs[1];

#pragma unroll
        for (int ks = 0; ks < 2; ks++) {
            uint32_t a[4] = { ph_lo[2 * ks], ph_hi[2 * ks],
                              ph_lo[2 * ks + 1], ph_hi[2 * ks + 1] };
#pragma unroll
            for (int p = 0; p < 8; p++) {
                uint32_t b0, b1, b2, b3;
                ldsm4(b0, b1, b2, b3,
                      vB + (uint32_t)(p * 16 * VSTRW * 4 + ks * 32));
                uint32_t bb0[2] = { b0, b1 }, bb1[2] = { b2, b3 };
                mma16(Oa[2 * p], a, bb0);
                mma16(Oa[2 * p + 1], a, bb1);
            }
        }
    }

    // ---- merge key halves (reuse dead K/V smem) -----------------------------
    __syncthreads();
    float* Mrg = (float*)(smu + KV_OFF);
    float* pbase = Mrg + qp * MRG_PAIR;
    if (half == 1) {
#pragma unroll
        for (int nt = 0; nt < 16; nt++) {
            int col = nt * 8 + lt * 2;
            *(float2*)&pbase[lg * MRG_STR + col]       = { Oa[nt][0], Oa[nt][1] };
            *(float2*)&pbase[(lg + 8) * MRG_STR + col] = { Oa[nt][2], Oa[nt][3] };
        }
        if (lt == 0) {
            *(float2*)&pbase[16 * MRG_STR + lg * 2]       = { m_run[0], l_run[0] };
            *(float2*)&pbase[16 * MRG_STR + (lg + 8) * 2] = { m_run[1], l_run[1] };
        }
    }
    __syncthreads();
    if (half == 0) {
        float2 mlB0 = *(float2*)&pbase[16 * MRG_STR + lg * 2];
        float2 mlB1 = *(float2*)&pbase[16 * MRG_STR + (lg + 8) * 2];
        float m0 = fmaxf(m_run[0], mlB0.x);
        float m1 = fmaxf(m_run[1], mlB1.x);
        float fA0 = exp2f(m_run[0] - m0), fB0 = exp2f(mlB0.x - m0);
        float fA1 = exp2f(m_run[1] - m1), fB1 = exp2f(mlB1.x - m1);
        float inv0 = 1.f / (l_run[0] * fA0 + mlB0.y * fB0);
        float inv1 = 1.f / (l_run[1] * fA1 + mlB1.y * fB1);

        int row = q0 + qp * 16 + lg;
        float* ob0 = out + ((size_t)(b * S_ + row)) * H_ + h * HD_;
        float* ob1 = out + ((size_t)(b * S_ + row + 8)) * H_ + h * HD_;
#pragma unroll
        for (int nt = 0; nt < 16; nt++) {
            int col = nt * 8 + lt * 2;
            float2 OB0 = *(float2*)&pbase[lg * MRG_STR + col];
            float2 OB1 = *(float2*)&pbase[(lg + 8) * MRG_STR + col];
            float2 o0 = { (Oa[nt][0] * fA0 + OB0.x * fB0) * inv0,
                          (Oa[nt][1] * fA0 + OB0.y * fB0) * inv0 };
            float2 o1 = { (Oa[nt][2] * fA1 + OB1.x * fB1) * inv1,
                          (Oa[nt][3] * fA1 + OB1.y * fB1) * inv1 };
            *(float2*)&ob0[col] = o0;
            *(float2*)&ob1[col] = o1;
        }
    }
}

// ---------------------------------------------------------------------------
extern "C" void kernel_launch(void* const* d_in, const int* in_sizes, int n_in,
                              void* d_out, int out_size)
{
    const float* X     = (const float*)d_in[0];
    const int*   amask = (const int*)  d_in[1];
    const float* Wq    = (const float*)d_in[2];
    const float* bq    = (const float*)d_in[3];
    const float* Wk    = (const float*)d_in[4];
    const float* bk    = (const float*)d_in[5];
    const float* Wv    = (const float*)d_in[6];
    const float* bv    = (const float*)d_in[7];
    float* out = (float*)d_out;

    __half *Qp, *Kp, *Vp, *Xh, *Wqh, *Wkh, *Wvh;
    cudaGetSymbolAddress((void**)&Qp, g_Qh);
    cudaGetSymbolAddress((void**)&Kp, g_Kh);
    cudaGetSymbolAddress((void**)&Vp, g_Vt);
    cudaGetSymbolAddress((void**)&Xh, g_Xh);
    cudaGetSymbolAddress((void**)&Wqh, g_Wqh);
    cudaGetSymbolAddress((void**)&Wkh, g_Wkh);
    cudaGetSymbolAddress((void**)&Wvh, g_Wvh);

    cvt_all<<<CVT_NB, 256>>>((const float4*)X, (const float4*)Wq,
                             (const float4*)Wk, (const float4*)Wv,
                             (uint4*)Xh, (uint4*)Wqh, (uint4*)Wkh, (uint4*)Wvh);

    cudaFuncSetAttribute(gemm_qkv,
                         cudaFuncAttributeMaxDynamicSharedMemorySize, GEMM_SMEM);
    gemm_qkv<<<dim3(24, M_ / 128), 256, GEMM_SMEM>>>(
        Xh, Wqh, Wkh, Wvh, bq, bk, bv, Qp, Kp, Vp);

    cudaFuncSetAttribute(attn_f16,
                         cudaFuncAttributeMaxDynamicSharedMemorySize, ATT_SMEM);
    attn_f16<<<dim3(S_ / ABM, NH_, B_), 256, ATT_SMEM>>>(Qp, Kp, Vp, amask, out);
}